// round 6
// baseline (speedup 1.0000x reference)
#include <cuda_runtime.h>

// ---------------------------------------------------------------------------
// MultiHeadAttention, fp32 end-to-end.
//   B=4, L=2048, H=16, d_k=64, d_model=1024, causal mask (tril).
// Stages:
//   1) Q = x@Wq+bq, K = x@Wk+bk, V = x@Wv+bv   (head-major scratch [B,H,L,64])
//   2) causal flash-attention -> ctx scratch [B,L,1024]
//   3) out = ctx@Wo + bo
// ---------------------------------------------------------------------------

#define DMODEL 1024
#define NHEADS 16
#define DK     64
#define BATCH  4
#define SEQ    2048
#define MROWS  (BATCH * SEQ)   // 8192

// Scratch (device globals; no runtime allocation allowed).
__device__ __align__(16) float g_Q[(size_t)BATCH * NHEADS * SEQ * DK];
__device__ __align__(16) float g_K[(size_t)BATCH * NHEADS * SEQ * DK];
__device__ __align__(16) float g_V[(size_t)BATCH * NHEADS * SEQ * DK];
__device__ __align__(16) float g_C[(size_t)BATCH * SEQ * DMODEL];

// ---------------------------------------------------------------------------
// GEMM: out = A[M,K] @ W[K,N] + bias[N]
// BM=128, BN=128, BK=16, 256 threads, 8x8 per-thread tile (two 4-wide panels).
// mode 0: plain row-major out[m*N + n]
// mode 1: head-split out[((b*16 + h)*SEQ + l)*64 + d],  m=b*SEQ+l, n=h*64+d
// All dims divide the tile sizes exactly (8192/128, 1024/128, 1024/16).
// ---------------------------------------------------------------------------
#define GM_BM 128
#define GM_BN 128
#define GM_BK 16

__global__ __launch_bounds__(256)
void gemm_bias_kernel(const float* __restrict__ A, const float* __restrict__ W,
                      const float* __restrict__ bias, float* __restrict__ out,
                      int M, int N, int K, int mode)
{
    __shared__ float As[GM_BK][GM_BM];   // transposed A tile
    __shared__ float Bs[GM_BK][GM_BN];

    const int tid = threadIdx.x;
    const int tx = tid & 15;        // 0..15 -> cols {tx*4..+3} and {64+tx*4..+3}
    const int ty = tid >> 4;        // 0..15 -> rows ty*8..ty*8+7
    const int m0 = blockIdx.y * GM_BM;
    const int n0 = blockIdx.x * GM_BN;

    float acc[8][8];
    #pragma unroll
    for (int i = 0; i < 8; ++i)
        #pragma unroll
        for (int j = 0; j < 8; ++j) acc[i][j] = 0.0f;

    for (int k0 = 0; k0 < K; k0 += GM_BK) {
        // Load A tile (128x16), store transposed. 2 float4 per thread.
        #pragma unroll
        for (int q = 0; q < 2; ++q) {
            int f   = tid * 2 + q;        // 0..511
            int row = f >> 2;             // 0..127
            int kq  = (f & 3) << 2;       // 0,4,8,12
            float4 v = *(const float4*)&A[(size_t)(m0 + row) * K + k0 + kq];
            As[kq + 0][row] = v.x;
            As[kq + 1][row] = v.y;
            As[kq + 2][row] = v.z;
            As[kq + 3][row] = v.w;
        }
        // Load W tile (16x128). 2 float4 per thread.
        #pragma unroll
        for (int q = 0; q < 2; ++q) {
            int f   = tid * 2 + q;        // 0..511
            int row = f >> 5;             // 0..15
            int nq  = (f & 31) << 2;      // 0..124
            *(float4*)&Bs[row][nq] =
                *(const float4*)&W[(size_t)(k0 + row) * N + n0 + nq];
        }
        __syncthreads();

        #pragma unroll
        for (int kk = 0; kk < GM_BK; ++kk) {
            float a[8], b[8];
            *(float4*)&a[0] = *(const float4*)&As[kk][ty * 8];
            *(float4*)&a[4] = *(const float4*)&As[kk][ty * 8 + 4];
            *(float4*)&b[0] = *(const float4*)&Bs[kk][tx * 4];        // panel 0
            *(float4*)&b[4] = *(const float4*)&Bs[kk][64 + tx * 4];   // panel 1
            #pragma unroll
            for (int i = 0; i < 8; ++i)
                #pragma unroll
                for (int j = 0; j < 8; ++j)
                    acc[i][j] += a[i] * b[j];
        }
        __syncthreads();
    }

    // Epilogue: two 4-wide column panels per thread.
    const float4 bb0 = *(const float4*)&bias[n0 + tx * 4];
    const float4 bb1 = *(const float4*)&bias[n0 + 64 + tx * 4];
    const int n1 = n0 + tx * 4;
    const int n2 = n0 + 64 + tx * 4;
    #pragma unroll
    for (int i = 0; i < 8; ++i) {
        int m = m0 + ty * 8 + i;
        float4 r0, r1;
        r0.x = acc[i][0] + bb0.x;  r0.y = acc[i][1] + bb0.y;
        r0.z = acc[i][2] + bb0.z;  r0.w = acc[i][3] + bb0.w;
        r1.x = acc[i][4] + bb1.x;  r1.y = acc[i][5] + bb1.y;
        r1.z = acc[i][6] + bb1.z;  r1.w = acc[i][7] + bb1.w;
        if (mode == 1) {
            int b_ = m >> 11;            // / SEQ
            int l_ = m & (SEQ - 1);
            int h1 = n1 >> 6, d1 = n1 & (DK - 1);
            int h2 = n2 >> 6, d2 = n2 & (DK - 1);
            *(float4*)&out[(((size_t)(b_ * NHEADS + h1) * SEQ + l_) * DK) + d1] = r0;
            *(float4*)&out[(((size_t)(b_ * NHEADS + h2) * SEQ + l_) * DK) + d2] = r1;
        } else {
            *(float4*)&out[(size_t)m * N + n1] = r0;
            *(float4*)&out[(size_t)m * N + n2] = r1;
        }
    }
}

// ---------------------------------------------------------------------------
// Causal flash attention.
// grid: (32 q-tiles, 64 bh). 256 threads (16x16). 64-row Q tile, 64-key K tile.
// Smem rows padded to stride 76 floats -> conflict-free LDS.128 patterns.
// P tile reuses the K buffer after S is computed.
// ---------------------------------------------------------------------------
#define ARS 76
#define ATTN_SMEM (3 * 64 * ARS * 4)   // 58368 bytes

__global__ __launch_bounds__(256)
void attn_kernel(const float* __restrict__ Q, const float* __restrict__ K,
                 const float* __restrict__ V, float* __restrict__ O)
{
    extern __shared__ float sm[];
    float* Qs = sm;                  // [64][ARS]
    float* KP = sm + 64 * ARS;       // K tile, then P tile
    float* Vs = sm + 2 * 64 * ARS;   // [64][ARS]

    const int tid = threadIdx.x;
    const int tx = tid & 15;         // key-col group (S) / d group (O)
    const int ty = tid >> 4;         // query-row group
    const int bh = blockIdx.y;
    const int qt = (int)gridDim.x - 1 - (int)blockIdx.x;  // longest tiles first
    const int q0 = qt * 64;
    const size_t base = (size_t)bh * SEQ * DK;

    // Load Q tile (64x64)
    for (int f = tid; f < 64 * 16; f += 256) {
        int row = f >> 4;
        int d4  = (f & 15) << 2;
        *(float4*)&Qs[row * ARS + d4] =
            *(const float4*)&Q[base + (size_t)(q0 + row) * DK + d4];
    }

    float m_i[4], l_i[4], o[4][4];
    #pragma unroll
    for (int i = 0; i < 4; ++i) {
        m_i[i] = -3.402823466e38f;
        l_i[i] = 0.0f;
        #pragma unroll
        for (int j = 0; j < 4; ++j) o[i][j] = 0.0f;
    }

    for (int j = 0; j <= qt; ++j) {
        const int k0 = j * 64;
        __syncthreads();  // prev iter done reading KP/Vs (also covers Qs load)

        // Load K and V tiles (64x64 each)
        for (int f = tid; f < 64 * 16; f += 256) {
            int row = f >> 4;
            int d4  = (f & 15) << 2;
            size_t g = base + (size_t)(k0 + row) * DK + d4;
            *(float4*)&KP[row * ARS + d4] = *(const float4*)&K[g];
            *(float4*)&Vs[row * ARS + d4] = *(const float4*)&V[g];
        }
        __syncthreads();

        // S = Q @ K^T (4x4 per thread)
        float s[4][4];
        #pragma unroll
        for (int i = 0; i < 4; ++i)
            #pragma unroll
            for (int c = 0; c < 4; ++c) s[i][c] = 0.0f;

        #pragma unroll 4
        for (int d = 0; d < DK; d += 4) {
            float4 qv[4], kv[4];
            #pragma unroll
            for (int i = 0; i < 4; ++i)
                qv[i] = *(const float4*)&Qs[(ty * 4 + i) * ARS + d];
            #pragma unroll
            for (int c = 0; c < 4; ++c)
                kv[c] = *(const float4*)&KP[(tx * 4 + c) * ARS + d];
            #pragma unroll
            for (int i = 0; i < 4; ++i)
                #pragma unroll
                for (int c = 0; c < 4; ++c)
                    s[i][c] += qv[i].x * kv[c].x + qv[i].y * kv[c].y
                             + qv[i].z * kv[c].z + qv[i].w * kv[c].w;
        }

        // Scale + causal mask (diagonal tile only; j<qt fully visible)
        const bool diag = (j == qt);
        #pragma unroll
        for (int i = 0; i < 4; ++i)
            #pragma unroll
            for (int c = 0; c < 4; ++c) {
                float v = s[i][c] * 0.125f;   // 1/sqrt(64)
                if (diag && (tx * 4 + c > ty * 4 + i)) v = -3.402823466e38f;
                s[i][c] = v;
            }

        // Online softmax update (row reductions via shfl across the 16 tx lanes;
        // lanes 0-15 and 16-31 of each warp hold two distinct ty groups, and
        // xor offsets 1,2,4,8 stay within each 16-lane half).
        #pragma unroll
        for (int i = 0; i < 4; ++i) {
            float mt = fmaxf(fmaxf(s[i][0], s[i][1]), fmaxf(s[i][2], s[i][3]));
            #pragma unroll
            for (int off = 1; off < 16; off <<= 1)
                mt = fmaxf(mt, __shfl_xor_sync(0xffffffffu, mt, off));
            float mn = fmaxf(m_i[i], mt);
            float corr = __expf(m_i[i] - mn);
            m_i[i] = mn;
            l_i[i] *= corr;
            #pragma unroll
            for (int c = 0; c < 4; ++c) o[i][c] *= corr;
            float rs = 0.0f;
            #pragma unroll
            for (int c = 0; c < 4; ++c) {
                s[i][c] = __expf(s[i][c] - mn);
                rs += s[i][c];
            }
            #pragma unroll
            for (int off = 1; off < 16; off <<= 1)
                rs += __shfl_xor_sync(0xffffffffu, rs, off);
            l_i[i] += rs;
        }

        __syncthreads();   // everyone done reading KP as K
        #pragma unroll
        for (int i = 0; i < 4; ++i)
            *(float4*)&KP[(ty * 4 + i) * ARS + tx * 4] =
                make_float4(s[i][0], s[i][1], s[i][2], s[i][3]);
        __syncthreads();   // P visible

        // O += P @ V  (thread's O cols are d = tx*4..tx*4+3)
        #pragma unroll 4
        for (int kk = 0; kk < 64; kk += 4) {
            float4 pv[4], vv[4];
            #pragma unroll
            for (int i = 0; i < 4; ++i)
                pv[i] = *(const float4*)&KP[(ty * 4 + i) * ARS + kk];
            #pragma unroll
            for (int c = 0; c < 4; ++c)
                vv[c] = *(const float4*)&Vs[(kk + c) * ARS + tx * 4];
            #pragma unroll
            for (int i = 0; i < 4; ++i) {
                o[i][0] += pv[i].x * vv[0].x + pv[i].y * vv[1].x
                         + pv[i].z * vv[2].x + pv[i].w * vv[3].x;
                o[i][1] += pv[i].x * vv[0].y + pv[i].y * vv[1].y
                         + pv[i].z * vv[2].y + pv[i].w * vv[3].y;
                o[i][2] += pv[i].x * vv[0].z + pv[i].y * vv[1].z
                         + pv[i].z * vv[2].z + pv[i].w * vv[3].z;
                o[i][3] += pv[i].x * vv[0].w + pv[i].y * vv[1].w
                         + pv[i].z * vv[2].w + pv[i].w * vv[3].w;
            }
        }
    }

    // Normalize + write ctx [B, L, 1024] (col = h*64 + d)
    const int b_ = bh >> 4;
    const int h_ = bh & 15;
    #pragma unroll
    for (int i = 0; i < 4; ++i) {
        float inv = 1.0f / l_i[i];
        int row = q0 + ty * 4 + i;
        float4 r = make_float4(o[i][0] * inv, o[i][1] * inv,
                               o[i][2] * inv, o[i][3] * inv);
        *(float4*)&O[((size_t)(b_ * SEQ + row)) * DMODEL + h_ * DK + tx * 4] = r;
    }
}

// ---------------------------------------------------------------------------
extern "C" void kernel_launch(void* const* d_in, const int* in_sizes, int n_in,
                              void* d_out, int out_size)
{
    (void)in_sizes; (void)n_in; (void)out_size;
    const float* x  = (const float*)d_in[0];
    // d_in[1] = mask (int32 tril; causal handled analytically)
    const float* Wq = (const float*)d_in[2];
    const float* bq = (const float*)d_in[3];
    const float* Wk = (const float*)d_in[4];
    const float* bk = (const float*)d_in[5];
    const float* Wv = (const float*)d_in[6];
    const float* bv = (const float*)d_in[7];
    const float* Wo = (const float*)d_in[8];
    const float* bo = (const float*)d_in[9];
    float* out = (float*)d_out;

    float *Qb, *Kb, *Vb, *Cb;
    cudaGetSymbolAddress((void**)&Qb, g_Q);
    cudaGetSymbolAddress((void**)&Kb, g_K);
    cudaGetSymbolAddress((void**)&Vb, g_V);
    cudaGetSymbolAddress((void**)&Cb, g_C);

    cudaFuncSetAttribute(attn_kernel,
                         cudaFuncAttributeMaxDynamicSharedMemorySize, ATTN_SMEM);

    dim3 ggrid(DMODEL / GM_BN, MROWS / GM_BM);   // (8, 64)
    gemm_bias_kernel<<<ggrid, 256>>>(x, Wq, bq, Qb, MROWS, DMODEL, DMODEL, 1);
    gemm_bias_kernel<<<ggrid, 256>>>(x, Wk, bk, Kb, MROWS, DMODEL, DMODEL, 1);
    gemm_bias_kernel<<<ggrid, 256>>>(x, Wv, bv, Vb, MROWS, DMODEL, DMODEL, 1);

    attn_kernel<<<dim3(SEQ / 64, BATCH * NHEADS), 256, ATTN_SMEM>>>(Qb, Kb, Vb, Cb);

    gemm_bias_kernel<<<ggrid, 256>>>(Cb, Wo, bo, out, MROWS, DMODEL, DMODEL, 0);
}

// round 9
// speedup vs baseline: 1.3116x; 1.3116x over previous
#include <cuda_runtime.h>
#include <cuda_bf16.h>
#include <cstdint>

typedef unsigned int u32;

// ---------------------------------------------------------------------------
// MultiHeadAttention. B=4, L=2048, H=16, d_k=64, d_model=1024, causal.
//   1) split x -> bf16 (hi, lo); split+transpose W -> bf16 (hi, lo)
//   2) Q/K/V = tensor-core split-bf16 GEMM (3 MMAs: hh + hl + lh), fp32 accum
//   3) causal flash-attention (fp32 SIMT, unchanged from R6 baseline)
//   4) split ctx -> bf16; out = split-bf16 GEMM + bo
// Split precision: a = a_hi + a_lo captures ~16 mantissa bits; dropping
// a_lo*b_lo leaves ~2^-18 relative error per product -> ~1e-5 end-to-end.
// ---------------------------------------------------------------------------

#define DMODEL 1024
#define NHEADS 16
#define DK     64
#define BATCH  4
#define SEQ    2048
#define MROWS  (BATCH * SEQ)   // 8192

// Scratch (device globals; no runtime allocation allowed).
__device__ __align__(16) float g_Q[(size_t)BATCH * NHEADS * SEQ * DK];
__device__ __align__(16) float g_K[(size_t)BATCH * NHEADS * SEQ * DK];
__device__ __align__(16) float g_V[(size_t)BATCH * NHEADS * SEQ * DK];
__device__ __align__(16) float g_C[(size_t)BATCH * SEQ * DMODEL];
__device__ __align__(16) __nv_bfloat16 g_ah[(size_t)MROWS * DMODEL];     // A hi
__device__ __align__(16) __nv_bfloat16 g_al[(size_t)MROWS * DMODEL];     // A lo
__device__ __align__(16) __nv_bfloat16 g_wh[4][(size_t)DMODEL * DMODEL]; // W^T hi
__device__ __align__(16) __nv_bfloat16 g_wl[4][(size_t)DMODEL * DMODEL]; // W^T lo

// ---------------------------------------------------------------------------
// PTX wrappers (inline functions with reference-array params; nvcc-safe).
// ---------------------------------------------------------------------------
__device__ __forceinline__ void ldm4(u32 (&r)[4], u32 addr)
{
    asm volatile("ldmatrix.sync.aligned.m8n8.x4.shared.b16 {%0,%1,%2,%3}, [%4];"
                 : "=r"(r[0]), "=r"(r[1]), "=r"(r[2]), "=r"(r[3])
                 : "r"(addr));
}

__device__ __forceinline__ void mma16816(float (&d)[4], const u32 (&a)[4],
                                         u32 b0, u32 b1)
{
    asm volatile("mma.sync.aligned.m16n8k16.row.col.f32.bf16.bf16.f32 "
                 "{%0,%1,%2,%3},{%4,%5,%6,%7},{%8,%9},{%0,%1,%2,%3};"
                 : "+f"(d[0]), "+f"(d[1]), "+f"(d[2]), "+f"(d[3])
                 : "r"(a[0]), "r"(a[1]), "r"(a[2]), "r"(a[3]),
                   "r"(b0), "r"(b1));
}

// ---------------------------------------------------------------------------
// Elementwise fp32 -> (bf16 hi, bf16 lo) split, 4 elems/thread.
// ---------------------------------------------------------------------------
union Pack4 { __nv_bfloat16 b[4]; uint2 u; };

__global__ void split_kernel(const float4* __restrict__ src,
                             uint2* __restrict__ hi, uint2* __restrict__ lo)
{
    int i = blockIdx.x * blockDim.x + threadIdx.x;
    float4 v = src[i];
    float vv[4] = {v.x, v.y, v.z, v.w};
    Pack4 H, L;
    #pragma unroll
    for (int j = 0; j < 4; ++j) {
        __nv_bfloat16 h = __float2bfloat16(vv[j]);
        H.b[j] = h;
        L.b[j] = __float2bfloat16(vv[j] - __bfloat162float(h));
    }
    hi[i] = H.u;
    lo[i] = L.u;
}

// ---------------------------------------------------------------------------
// W [K,N] fp32 -> W^T [N,K] bf16 hi/lo. 32x32 tiles, block (32,8).
// ---------------------------------------------------------------------------
__global__ void wsplit_kernel(const float* __restrict__ W,
                              __nv_bfloat16* __restrict__ th,
                              __nv_bfloat16* __restrict__ tl)
{
    __shared__ float t[32][33];
    const int tx = threadIdx.x, ty = threadIdx.y;
    const int bx = blockIdx.x * 32, by = blockIdx.y * 32;
    #pragma unroll
    for (int i = 0; i < 32; i += 8)
        t[ty + i][tx] = W[(size_t)(by + ty + i) * DMODEL + bx + tx];
    __syncthreads();
    #pragma unroll
    for (int i = 0; i < 32; i += 8) {
        float v = t[tx][ty + i];
        int n = bx + ty + i, k = by + tx;
        __nv_bfloat16 h = __float2bfloat16(v);
        th[(size_t)n * DMODEL + k] = h;
        tl[(size_t)n * DMODEL + k] = __float2bfloat16(v - __bfloat162float(h));
    }
}

// ---------------------------------------------------------------------------
// Split-bf16 tensor-core GEMM: out[M=8192, N=1024] = A @ B^T + bias
//   A as (Ah+Al)[m][k] row-major bf16, B as (Bh+Bl)[n][k] row-major bf16.
//   acc += Ah*Bh + Ah*Bl + Al*Bh   (fp32 accum via mma.m16n8k16)
// BM=128, BN=128, BK=32, 256 threads = 8 warps (4 m x 2 n), warp tile 32x64.
// Smem rows padded to 40 halves (80 B) -> conflict-free ldmatrix phases
// (row banks {0,20,8,28,16,4,24,12} x4-wide cover all 32 banks).
// mode 0: out[m*1024+n]; mode 1: head-split out[((b*16+h)*2048+l)*64+d].
// ---------------------------------------------------------------------------
__global__ __launch_bounds__(256)
void gemm_bf16_split(const __nv_bfloat16* __restrict__ Ah,
                     const __nv_bfloat16* __restrict__ Al,
                     const __nv_bfloat16* __restrict__ Bh,
                     const __nv_bfloat16* __restrict__ Bl,
                     const float* __restrict__ bias,
                     float* __restrict__ out, int mode)
{
    __shared__ __align__(16) __nv_bfloat16 smA_h[128 * 40];
    __shared__ __align__(16) __nv_bfloat16 smA_l[128 * 40];
    __shared__ __align__(16) __nv_bfloat16 smB_h[128 * 40];
    __shared__ __align__(16) __nv_bfloat16 smB_l[128 * 40];

    const int tid  = threadIdx.x;
    const int lane = tid & 31;
    const int warp = tid >> 5;
    const int wm   = warp >> 1;      // 0..3 -> rows wm*32..+32
    const int wn   = warp & 1;       // 0..1 -> cols wn*64..+64
    const int m0   = blockIdx.y * 128;
    const int n0   = blockIdx.x * 128;

    const int rb = tid >> 2;          // 0..63 (+64 for q=1)
    const int c8 = (tid & 3) << 3;    // 0,8,16,24 halves

    const u32 sa_h = (u32)__cvta_generic_to_shared(smA_h);
    const u32 sa_l = (u32)__cvta_generic_to_shared(smA_l);
    const u32 sb_h = (u32)__cvta_generic_to_shared(smB_h);
    const u32 sb_l = (u32)__cvta_generic_to_shared(smB_l);

    // ldmatrix per-lane row offsets (in halves); tile = lane>>3.
    // A (m16 x k16): tiles {r0/k0, r8/k0, r0/k8, r8/k8}  -> regs a0..a3
    const int tr = lane & 7;
    const int arow = (wm * 32 + ((lane >> 3) & 1) * 8 + tr) * 40
                   + ((lane >> 4) & 1) * 8;
    // B (n16 pair x k16): tiles {n0/k0, n0/k8, n8/k0, n8/k8} -> b0,b1 per nfrag
    int brow[4];
    #pragma unroll
    for (int p = 0; p < 4; ++p)
        brow[p] = (wn * 64 + p * 16 + ((lane >> 4) & 1) * 8 + tr) * 40
                + ((lane >> 3) & 1) * 8;

    float acc[2][8][4];
    #pragma unroll
    for (int mi = 0; mi < 2; ++mi)
        #pragma unroll
        for (int ni = 0; ni < 8; ++ni)
            #pragma unroll
            for (int r = 0; r < 4; ++r) acc[mi][ni][r] = 0.0f;

    uint4 pr[8];

#define LDG_CHUNK(k0) do {                                                  \
    _Pragma("unroll")                                                       \
    for (int q = 0; q < 2; ++q) {                                           \
        size_t ga = (size_t)(m0 + rb + 64 * q) * DMODEL + (k0) + c8;        \
        size_t gb = (size_t)(n0 + rb + 64 * q) * DMODEL + (k0) + c8;        \
        pr[q]     = *(const uint4*)(Ah + ga);                               \
        pr[2 + q] = *(const uint4*)(Al + ga);                               \
        pr[4 + q] = *(const uint4*)(Bh + gb);                               \
        pr[6 + q] = *(const uint4*)(Bl + gb);                               \
    } } while (0)

#define STS_CHUNK() do {                                                    \
    _Pragma("unroll")                                                       \
    for (int q = 0; q < 2; ++q) {                                           \
        int so = (rb + 64 * q) * 40 + c8;                                   \
        *(uint4*)&smA_h[so] = pr[q];                                        \
        *(uint4*)&smA_l[so] = pr[2 + q];                                    \
        *(uint4*)&smB_h[so] = pr[4 + q];                                    \
        *(uint4*)&smB_l[so] = pr[6 + q];                                    \
    } } while (0)

    LDG_CHUNK(0);
    STS_CHUNK();
    __syncthreads();

    for (int kc = 0; kc < DMODEL / 32; ++kc) {
        if (kc < DMODEL / 32 - 1) LDG_CHUNK((kc + 1) * 32);

        #pragma unroll
        for (int ks = 0; ks < 2; ++ks) {
            const int ko = ks * 16;
            u32 fa_h0[4], fa_h1[4], fa_l0[4], fa_l1[4];
            ldm4(fa_h0, sa_h + (u32)(arow + ko) * 2);
            ldm4(fa_h1, sa_h + (u32)(arow + 640 + ko) * 2);   // +16 rows * 40
            ldm4(fa_l0, sa_l + (u32)(arow + ko) * 2);
            ldm4(fa_l1, sa_l + (u32)(arow + 640 + ko) * 2);
            #pragma unroll
            for (int p = 0; p < 4; ++p) {
                u32 fbh[4], fbl[4];
                ldm4(fbh, sb_h + (u32)(brow[p] + ko) * 2);
                ldm4(fbl, sb_l + (u32)(brow[p] + ko) * 2);
                // nfrag 2p uses (fb[0], fb[1]); nfrag 2p+1 uses (fb[2], fb[3])
                mma16816(acc[0][2 * p],     fa_h0, fbh[0], fbh[1]);
                mma16816(acc[0][2 * p],     fa_h0, fbl[0], fbl[1]);
                mma16816(acc[0][2 * p],     fa_l0, fbh[0], fbh[1]);
                mma16816(acc[0][2 * p + 1], fa_h0, fbh[2], fbh[3]);
                mma16816(acc[0][2 * p + 1], fa_h0, fbl[2], fbl[3]);
                mma16816(acc[0][2 * p + 1], fa_l0, fbh[2], fbh[3]);
                mma16816(acc[1][2 * p],     fa_h1, fbh[0], fbh[1]);
                mma16816(acc[1][2 * p],     fa_h1, fbl[0], fbl[1]);
                mma16816(acc[1][2 * p],     fa_l1, fbh[0], fbh[1]);
                mma16816(acc[1][2 * p + 1], fa_h1, fbh[2], fbh[3]);
                mma16816(acc[1][2 * p + 1], fa_h1, fbl[2], fbl[3]);
                mma16816(acc[1][2 * p + 1], fa_l1, fbh[2], fbh[3]);
            }
        }
        __syncthreads();
        if (kc < DMODEL / 32 - 1) { STS_CHUNK(); __syncthreads(); }
    }
#undef LDG_CHUNK
#undef STS_CHUNK

    // Epilogue. C frag: c0,c1 = row g, cols t2,t2+1; c2,c3 = row g+8.
    const int g  = lane >> 2;
    const int t2 = (lane & 3) * 2;
    #pragma unroll
    for (int mi = 0; mi < 2; ++mi) {
        #pragma unroll
        for (int ni = 0; ni < 8; ++ni) {
            int n = n0 + wn * 64 + ni * 8 + t2;
            float2 bb = *(const float2*)&bias[n];
            int m1 = m0 + wm * 32 + mi * 16 + g;
            int m2 = m1 + 8;
            float2 v0 = make_float2(acc[mi][ni][0] + bb.x, acc[mi][ni][1] + bb.y);
            float2 v1 = make_float2(acc[mi][ni][2] + bb.x, acc[mi][ni][3] + bb.y);
            if (mode == 1) {
                int h_ = n >> 6, d_ = n & (DK - 1);
                int b1 = m1 >> 11, l1 = m1 & (SEQ - 1);
                int b2 = m2 >> 11, l2 = m2 & (SEQ - 1);
                *(float2*)&out[(((size_t)(b1 * NHEADS + h_) * SEQ + l1) << 6) + d_] = v0;
                *(float2*)&out[(((size_t)(b2 * NHEADS + h_) * SEQ + l2) << 6) + d_] = v1;
            } else {
                *(float2*)&out[(size_t)m1 * DMODEL + n] = v0;
                *(float2*)&out[(size_t)m2 * DMODEL + n] = v1;
            }
        }
    }
}

// ---------------------------------------------------------------------------
// Causal flash attention (unchanged from R6 passing baseline).
// grid: (32 q-tiles, 64 bh). 256 threads (16x16). 64-row Q tile, 64-key tile.
// ---------------------------------------------------------------------------
#define ARS 76
#define ATTN_SMEM (3 * 64 * ARS * 4)   // 58368 bytes

__global__ __launch_bounds__(256)
void attn_kernel(const float* __restrict__ Q, const float* __restrict__ K,
                 const float* __restrict__ V, float* __restrict__ O)
{
    extern __shared__ float sm[];
    float* Qs = sm;                  // [64][ARS]
    float* KP = sm + 64 * ARS;       // K tile, then P tile
    float* Vs = sm + 2 * 64 * ARS;   // [64][ARS]

    const int tid = threadIdx.x;
    const int tx = tid & 15;
    const int ty = tid >> 4;
    const int bh = blockIdx.y;
    const int qt = (int)gridDim.x - 1 - (int)blockIdx.x;  // longest tiles first
    const int q0 = qt * 64;
    const size_t base = (size_t)bh * SEQ * DK;

    for (int f = tid; f < 64 * 16; f += 256) {
        int row = f >> 4;
        int d4  = (f & 15) << 2;
        *(float4*)&Qs[row * ARS + d4] =
            *(const float4*)&Q[base + (size_t)(q0 + row) * DK + d4];
    }

    float m_i[4], l_i[4], o[4][4];
    #pragma unroll
    for (int i = 0; i < 4; ++i) {
        m_i[i] = -3.402823466e38f;
        l_i[i] = 0.0f;
        #pragma unroll
        for (int j = 0; j < 4; ++j) o[i][j] = 0.0f;
    }

    for (int j = 0; j <= qt; ++j) {
        const int k0 = j * 64;
        __syncthreads();

        for (int f = tid; f < 64 * 16; f += 256) {
            int row = f >> 4;
            int d4  = (f & 15) << 2;
            size_t gidx = base + (size_t)(k0 + row) * DK + d4;
            *(float4*)&KP[row * ARS + d4] = *(const float4*)&K[gidx];
            *(float4*)&Vs[row * ARS + d4] = *(const float4*)&V[gidx];
        }
        __syncthreads();

        float s[4][4];
        #pragma unroll
        for (int i = 0; i < 4; ++i)
            #pragma unroll
            for (int c = 0; c < 4; ++c) s[i][c] = 0.0f;

        #pragma unroll 4
        for (int d = 0; d < DK; d += 4) {
            float4 qv[4], kv[4];
            #pragma unroll
            for (int i = 0; i < 4; ++i)
                qv[i] = *(const float4*)&Qs[(ty * 4 + i) * ARS + d];
            #pragma unroll
            for (int c = 0; c < 4; ++c)
                kv[c] = *(const float4*)&KP[(tx * 4 + c) * ARS + d];
            #pragma unroll
            for (int i = 0; i < 4; ++i)
                #pragma unroll
                for (int c = 0; c < 4; ++c)
                    s[i][c] += qv[i].x * kv[c].x + qv[i].y * kv[c].y
                             + qv[i].z * kv[c].z + qv[i].w * kv[c].w;
        }

        const bool diag = (j == qt);
        #pragma unroll
        for (int i = 0; i < 4; ++i)
            #pragma unroll
            for (int c = 0; c < 4; ++c) {
                float v = s[i][c] * 0.125f;
                if (diag && (tx * 4 + c > ty * 4 + i)) v = -3.402823466e38f;
                s[i][c] = v;
            }

        #pragma unroll
        for (int i = 0; i < 4; ++i) {
            float mt = fmaxf(fmaxf(s[i][0], s[i][1]), fmaxf(s[i][2], s[i][3]));
            #pragma unroll
            for (int off = 1; off < 16; off <<= 1)
                mt = fmaxf(mt, __shfl_xor_sync(0xffffffffu, mt, off));
            float mn = fmaxf(m_i[i], mt);
            float corr = __expf(m_i[i] - mn);
            m_i[i] = mn;
            l_i[i] *= corr;
            #pragma unroll
            for (int c = 0; c < 4; ++c) o[i][c] *= corr;
            float rs = 0.0f;
            #pragma unroll
            for (int c = 0; c < 4; ++c) {
                s[i][c] = __expf(s[i][c] - mn);
                rs += s[i][c];
            }
            #pragma unroll
            for (int off = 1; off < 16; off <<= 1)
                rs += __shfl_xor_sync(0xffffffffu, rs, off);
            l_i[i] += rs;
        }

        __syncthreads();
        #pragma unroll
        for (int i = 0; i < 4; ++i)
            *(float4*)&KP[(ty * 4 + i) * ARS + tx * 4] =
                make_float4(s[i][0], s[i][1], s[i][2], s[i][3]);
        __syncthreads();

        #pragma unroll 4
        for (int kk = 0; kk < 64; kk += 4) {
            float4 pv[4], vv[4];
            #pragma unroll
            for (int i = 0; i < 4; ++i)
                pv[i] = *(const float4*)&KP[(ty * 4 + i) * ARS + kk];
            #pragma unroll
            for (int c = 0; c < 4; ++c)
                vv[c] = *(const float4*)&Vs[(kk + c) * ARS + tx * 4];
            #pragma unroll
            for (int i = 0; i < 4; ++i) {
                o[i][0] += pv[i].x * vv[0].x + pv[i].y * vv[1].x
                         + pv[i].z * vv[2].x + pv[i].w * vv[3].x;
                o[i][1] += pv[i].x * vv[0].y + pv[i].y * vv[1].y
                         + pv[i].z * vv[2].y + pv[i].w * vv[3].y;
                o[i][2] += pv[i].x * vv[0].z + pv[i].y * vv[1].z
                         + pv[i].z * vv[2].z + pv[i].w * vv[3].z;
                o[i][3] += pv[i].x * vv[0].w + pv[i].y * vv[1].w
                         + pv[i].z * vv[2].w + pv[i].w * vv[3].w;
            }
        }
    }

    const int b_ = bh >> 4;
    const int h_ = bh & 15;
    #pragma unroll
    for (int i = 0; i < 4; ++i) {
        float inv = 1.0f / l_i[i];
        int row = q0 + ty * 4 + i;
        float4 r = make_float4(o[i][0] * inv, o[i][1] * inv,
                               o[i][2] * inv, o[i][3] * inv);
        *(float4*)&O[((size_t)(b_ * SEQ + row)) * DMODEL + h_ * DK + tx * 4] = r;
    }
}

// ---------------------------------------------------------------------------
extern "C" void kernel_launch(void* const* d_in, const int* in_sizes, int n_in,
                              void* d_out, int out_size)
{
    (void)in_sizes; (void)n_in; (void)out_size;
    const float* x  = (const float*)d_in[0];
    // d_in[1] = mask (int32 tril; causal handled analytically)
    const float* Wq = (const float*)d_in[2];
    const float* bq = (const float*)d_in[3];
    const float* Wk = (const float*)d_in[4];
    const float* bk = (const float*)d_in[5];
    const float* Wv = (const float*)d_in[6];
    const float* bv = (const float*)d_in[7];
    const float* Wo = (const float*)d_in[8];
    const float* bo = (const float*)d_in[9];
    float* out = (float*)d_out;

    float *Qb, *Kb, *Vb, *Cb;
    __nv_bfloat16 *ah, *al, *wh, *wl;
    cudaGetSymbolAddress((void**)&Qb, g_Q);
    cudaGetSymbolAddress((void**)&Kb, g_K);
    cudaGetSymbolAddress((void**)&Vb, g_V);
    cudaGetSymbolAddress((void**)&Cb, g_C);
    cudaGetSymbolAddress((void**)&ah, g_ah);
    cudaGetSymbolAddress((void**)&al, g_al);
    cudaGetSymbolAddress((void**)&wh, g_wh);
    cudaGetSymbolAddress((void**)&wl, g_wl);

    cudaFuncSetAttribute(attn_kernel,
                         cudaFuncAttributeMaxDynamicSharedMemorySize, ATTN_SMEM);

    const size_t WSZ = (size_t)DMODEL * DMODEL;
    const int n4 = MROWS * DMODEL / 4;   // 2097152 -> 8192 blocks of 256

    // Precompute bf16 splits.
    split_kernel<<<n4 / 256, 256>>>((const float4*)x, (uint2*)ah, (uint2*)al);
    dim3 wgrid(DMODEL / 32, DMODEL / 32), wblk(32, 8);
    wsplit_kernel<<<wgrid, wblk>>>(Wq, wh + 0 * WSZ, wl + 0 * WSZ);
    wsplit_kernel<<<wgrid, wblk>>>(Wk, wh + 1 * WSZ, wl + 1 * WSZ);
    wsplit_kernel<<<wgrid, wblk>>>(Wv, wh + 2 * WSZ, wl + 2 * WSZ);
    wsplit_kernel<<<wgrid, wblk>>>(Wo, wh + 3 * WSZ, wl + 3 * WSZ);

    // Projections (tensor cores, head-split epilogue).
    dim3 ggrid(DMODEL / 128, MROWS / 128);   // (8, 64)
    gemm_bf16_split<<<ggrid, 256>>>(ah, al, wh + 0 * WSZ, wl + 0 * WSZ, bq, Qb, 1);
    gemm_bf16_split<<<ggrid, 256>>>(ah, al, wh + 1 * WSZ, wl + 1 * WSZ, bk, Kb, 1);
    gemm_bf16_split<<<ggrid, 256>>>(ah, al, wh + 2 * WSZ, wl + 2 * WSZ, bv, Vb, 1);

    attn_kernel<<<dim3(SEQ / 64, BATCH * NHEADS), 256, ATTN_SMEM>>>(Qb, Kb, Vb, Cb);

    // Output projection.
    split_kernel<<<n4 / 256, 256>>>((const float4*)Cb, (uint2*)ah, (uint2*)al);
    gemm_bf16_split<<<ggrid, 256>>>(ah, al, wh + 3 * WSZ, wl + 3 * WSZ, bo, out, 0);
}

// round 10
// speedup vs baseline: 2.7249x; 2.0775x over previous
#include <cuda_runtime.h>
#include <cuda_bf16.h>
#include <cstdint>

typedef unsigned int u32;

// ---------------------------------------------------------------------------
// MultiHeadAttention. B=4, L=2048, H=16, d_k=64, d_model=1024, causal.
//   1) split x -> bf16 hi/lo; split+transpose W -> bf16 hi/lo
//   2) Q/K/V projections: split-bf16 MMA GEMM, epilogue stores Q/K/V as
//      split bf16 hi/lo in head-major [B,H,L,64]
//   3) causal flash-attention-2 on tensor cores (3-term split-bf16 S and PV,
//      fp32 softmax on register fragments) -> ctx [B,L,1024] fp32
//   4) split ctx -> bf16; out = split-bf16 GEMM + bo
// ---------------------------------------------------------------------------

#define DMODEL 1024
#define NHEADS 16
#define DK     64
#define BATCH  4
#define SEQ    2048
#define MROWS  (BATCH * SEQ)   // 8192

// Scratch (device globals; no runtime allocation allowed).
__device__ __align__(16) float g_C[(size_t)BATCH * SEQ * DMODEL];
__device__ __align__(16) __nv_bfloat16 g_ah[(size_t)MROWS * DMODEL];
__device__ __align__(16) __nv_bfloat16 g_al[(size_t)MROWS * DMODEL];
__device__ __align__(16) __nv_bfloat16 g_wh[4][(size_t)DMODEL * DMODEL];
__device__ __align__(16) __nv_bfloat16 g_wl[4][(size_t)DMODEL * DMODEL];
// Q/K/V head-major [B*H, L, 64], split hi/lo bf16.
#define QKV_ELEMS ((size_t)BATCH * NHEADS * SEQ * DK)
__device__ __align__(16) __nv_bfloat16 g_Qh[QKV_ELEMS];
__device__ __align__(16) __nv_bfloat16 g_Ql[QKV_ELEMS];
__device__ __align__(16) __nv_bfloat16 g_Kh[QKV_ELEMS];
__device__ __align__(16) __nv_bfloat16 g_Kl[QKV_ELEMS];
__device__ __align__(16) __nv_bfloat16 g_Vh[QKV_ELEMS];
__device__ __align__(16) __nv_bfloat16 g_Vl[QKV_ELEMS];

// ---------------------------------------------------------------------------
// PTX wrappers (validated in R9; ldm4t is the .trans variant for V).
// ---------------------------------------------------------------------------
__device__ __forceinline__ void ldm4(u32 (&r)[4], u32 addr)
{
    asm volatile("ldmatrix.sync.aligned.m8n8.x4.shared.b16 {%0,%1,%2,%3}, [%4];"
                 : "=r"(r[0]), "=r"(r[1]), "=r"(r[2]), "=r"(r[3])
                 : "r"(addr));
}

__device__ __forceinline__ void ldm4t(u32 (&r)[4], u32 addr)
{
    asm volatile("ldmatrix.sync.aligned.m8n8.x4.trans.shared.b16 {%0,%1,%2,%3}, [%4];"
                 : "=r"(r[0]), "=r"(r[1]), "=r"(r[2]), "=r"(r[3])
                 : "r"(addr));
}

__device__ __forceinline__ void mma16816(float (&d)[4], const u32 (&a)[4],
                                         u32 b0, u32 b1)
{
    asm volatile("mma.sync.aligned.m16n8k16.row.col.f32.bf16.bf16.f32 "
                 "{%0,%1,%2,%3},{%4,%5,%6,%7},{%8,%9},{%0,%1,%2,%3};"
                 : "+f"(d[0]), "+f"(d[1]), "+f"(d[2]), "+f"(d[3])
                 : "r"(a[0]), "r"(a[1]), "r"(a[2]), "r"(a[3]),
                   "r"(b0), "r"(b1));
}

// Split two floats into packed bf16x2 hi and lo (low half = first element).
__device__ __forceinline__ void split2(float a, float b, u32& hi, u32& lo)
{
    __nv_bfloat16 ha = __float2bfloat16(a), hb = __float2bfloat16(b);
    __nv_bfloat16 la = __float2bfloat16(a - __bfloat162float(ha));
    __nv_bfloat16 lb = __float2bfloat16(b - __bfloat162float(hb));
    union { __nv_bfloat162 v; u32 u; } H, L;
    H.v.x = ha; H.v.y = hb; L.v.x = la; L.v.y = lb;
    hi = H.u; lo = L.u;
}

// ---------------------------------------------------------------------------
// Elementwise fp32 -> (bf16 hi, bf16 lo) split, 4 elems/thread.
// ---------------------------------------------------------------------------
union Pack4 { __nv_bfloat16 b[4]; uint2 u; };

__global__ void split_kernel(const float4* __restrict__ src,
                             uint2* __restrict__ hi, uint2* __restrict__ lo)
{
    int i = blockIdx.x * blockDim.x + threadIdx.x;
    float4 v = src[i];
    float vv[4] = {v.x, v.y, v.z, v.w};
    Pack4 H, L;
    #pragma unroll
    for (int j = 0; j < 4; ++j) {
        __nv_bfloat16 h = __float2bfloat16(vv[j]);
        H.b[j] = h;
        L.b[j] = __float2bfloat16(vv[j] - __bfloat162float(h));
    }
    hi[i] = H.u;
    lo[i] = L.u;
}

// ---------------------------------------------------------------------------
// W [K,N] fp32 -> W^T [N,K] bf16 hi/lo. 32x32 tiles, block (32,8).
// ---------------------------------------------------------------------------
__global__ void wsplit_kernel(const float* __restrict__ W,
                              __nv_bfloat16* __restrict__ th,
                              __nv_bfloat16* __restrict__ tl)
{
    __shared__ float t[32][33];
    const int tx = threadIdx.x, ty = threadIdx.y;
    const int bx = blockIdx.x * 32, by = blockIdx.y * 32;
    #pragma unroll
    for (int i = 0; i < 32; i += 8)
        t[ty + i][tx] = W[(size_t)(by + ty + i) * DMODEL + bx + tx];
    __syncthreads();
    #pragma unroll
    for (int i = 0; i < 32; i += 8) {
        float v = t[tx][ty + i];
        int n = bx + ty + i, k = by + tx;
        __nv_bfloat16 h = __float2bfloat16(v);
        th[(size_t)n * DMODEL + k] = h;
        tl[(size_t)n * DMODEL + k] = __float2bfloat16(v - __bfloat162float(h));
    }
}

// ---------------------------------------------------------------------------
// Split-bf16 tensor-core GEMM (validated in R9).
// mode 0: fp32 out[m*1024+n];  mode 1: split-bf16 head-major Q/K/V (oH, oL).
// ---------------------------------------------------------------------------
__global__ __launch_bounds__(256)
void gemm_bf16_split(const __nv_bfloat16* __restrict__ Ah,
                     const __nv_bfloat16* __restrict__ Al,
                     const __nv_bfloat16* __restrict__ Bh,
                     const __nv_bfloat16* __restrict__ Bl,
                     const float* __restrict__ bias,
                     float* __restrict__ out,
                     __nv_bfloat16* __restrict__ oH,
                     __nv_bfloat16* __restrict__ oL, int mode)
{
    __shared__ __align__(16) __nv_bfloat16 smA_h[128 * 40];
    __shared__ __align__(16) __nv_bfloat16 smA_l[128 * 40];
    __shared__ __align__(16) __nv_bfloat16 smB_h[128 * 40];
    __shared__ __align__(16) __nv_bfloat16 smB_l[128 * 40];

    const int tid  = threadIdx.x;
    const int lane = tid & 31;
    const int warp = tid >> 5;
    const int wm   = warp >> 1;
    const int wn   = warp & 1;
    const int m0   = blockIdx.y * 128;
    const int n0   = blockIdx.x * 128;

    const int rb = tid >> 2;
    const int c8 = (tid & 3) << 3;

    const u32 sa_h = (u32)__cvta_generic_to_shared(smA_h);
    const u32 sa_l = (u32)__cvta_generic_to_shared(smA_l);
    const u32 sb_h = (u32)__cvta_generic_to_shared(smB_h);
    const u32 sb_l = (u32)__cvta_generic_to_shared(smB_l);

    const int tr = lane & 7;
    const int arow = (wm * 32 + ((lane >> 3) & 1) * 8 + tr) * 40
                   + ((lane >> 4) & 1) * 8;
    int brow[4];
    #pragma unroll
    for (int p = 0; p < 4; ++p)
        brow[p] = (wn * 64 + p * 16 + ((lane >> 4) & 1) * 8 + tr) * 40
                + ((lane >> 3) & 1) * 8;

    float acc[2][8][4];
    #pragma unroll
    for (int mi = 0; mi < 2; ++mi)
        #pragma unroll
        for (int ni = 0; ni < 8; ++ni)
            #pragma unroll
            for (int r = 0; r < 4; ++r) acc[mi][ni][r] = 0.0f;

    uint4 pr[8];

#define LDG_CHUNK(k0) do {                                                  \
    _Pragma("unroll")                                                       \
    for (int q = 0; q < 2; ++q) {                                           \
        size_t ga = (size_t)(m0 + rb + 64 * q) * DMODEL + (k0) + c8;        \
        size_t gb = (size_t)(n0 + rb + 64 * q) * DMODEL + (k0) + c8;        \
        pr[q]     = *(const uint4*)(Ah + ga);                               \
        pr[2 + q] = *(const uint4*)(Al + ga);                               \
        pr[4 + q] = *(const uint4*)(Bh + gb);                               \
        pr[6 + q] = *(const uint4*)(Bl + gb);                               \
    } } while (0)

#define STS_CHUNK() do {                                                    \
    _Pragma("unroll")                                                       \
    for (int q = 0; q < 2; ++q) {                                           \
        int so = (rb + 64 * q) * 40 + c8;                                   \
        *(uint4*)&smA_h[so] = pr[q];                                        \
        *(uint4*)&smA_l[so] = pr[2 + q];                                    \
        *(uint4*)&smB_h[so] = pr[4 + q];                                    \
        *(uint4*)&smB_l[so] = pr[6 + q];                                    \
    } } while (0)

    LDG_CHUNK(0);
    STS_CHUNK();
    __syncthreads();

    for (int kc = 0; kc < DMODEL / 32; ++kc) {
        if (kc < DMODEL / 32 - 1) LDG_CHUNK((kc + 1) * 32);

        #pragma unroll
        for (int ks = 0; ks < 2; ++ks) {
            const int ko = ks * 16;
            u32 fa_h0[4], fa_h1[4], fa_l0[4], fa_l1[4];
            ldm4(fa_h0, sa_h + (u32)(arow + ko) * 2);
            ldm4(fa_h1, sa_h + (u32)(arow + 640 + ko) * 2);
            ldm4(fa_l0, sa_l + (u32)(arow + ko) * 2);
            ldm4(fa_l1, sa_l + (u32)(arow + 640 + ko) * 2);
            #pragma unroll
            for (int p = 0; p < 4; ++p) {
                u32 fbh[4], fbl[4];
                ldm4(fbh, sb_h + (u32)(brow[p] + ko) * 2);
                ldm4(fbl, sb_l + (u32)(brow[p] + ko) * 2);
                mma16816(acc[0][2 * p],     fa_h0, fbh[0], fbh[1]);
                mma16816(acc[0][2 * p],     fa_h0, fbl[0], fbl[1]);
                mma16816(acc[0][2 * p],     fa_l0, fbh[0], fbh[1]);
                mma16816(acc[0][2 * p + 1], fa_h0, fbh[2], fbh[3]);
                mma16816(acc[0][2 * p + 1], fa_h0, fbl[2], fbl[3]);
                mma16816(acc[0][2 * p + 1], fa_l0, fbh[2], fbh[3]);
                mma16816(acc[1][2 * p],     fa_h1, fbh[0], fbh[1]);
                mma16816(acc[1][2 * p],     fa_h1, fbl[0], fbl[1]);
                mma16816(acc[1][2 * p],     fa_l1, fbh[0], fbh[1]);
                mma16816(acc[1][2 * p + 1], fa_h1, fbh[2], fbh[3]);
                mma16816(acc[1][2 * p + 1], fa_h1, fbl[2], fbl[3]);
                mma16816(acc[1][2 * p + 1], fa_l1, fbh[2], fbh[3]);
            }
        }
        __syncthreads();
        if (kc < DMODEL / 32 - 1) { STS_CHUNK(); __syncthreads(); }
    }
#undef LDG_CHUNK
#undef STS_CHUNK

    const int g  = lane >> 2;
    const int t2 = (lane & 3) * 2;
    #pragma unroll
    for (int mi = 0; mi < 2; ++mi) {
        #pragma unroll
        for (int ni = 0; ni < 8; ++ni) {
            int n = n0 + wn * 64 + ni * 8 + t2;
            float2 bb = *(const float2*)&bias[n];
            int m1 = m0 + wm * 32 + mi * 16 + g;
            int m2 = m1 + 8;
            float2 v0 = make_float2(acc[mi][ni][0] + bb.x, acc[mi][ni][1] + bb.y);
            float2 v1 = make_float2(acc[mi][ni][2] + bb.x, acc[mi][ni][3] + bb.y);
            if (mode == 1) {
                int h_ = n >> 6, d_ = n & (DK - 1);
                int b1 = m1 >> 11, l1 = m1 & (SEQ - 1);
                int b2 = m2 >> 11, l2 = m2 & (SEQ - 1);
                size_t i1 = (((size_t)(b1 * NHEADS + h_) * SEQ + l1) << 6) + d_;
                size_t i2 = (((size_t)(b2 * NHEADS + h_) * SEQ + l2) << 6) + d_;
                u32 h0, l0, h1, l1p;
                split2(v0.x, v0.y, h0, l0);
                split2(v1.x, v1.y, h1, l1p);
                *(u32*)&oH[i1] = h0; *(u32*)&oL[i1] = l0;
                *(u32*)&oH[i2] = h1; *(u32*)&oL[i2] = l1p;
            } else {
                *(float2*)&out[(size_t)m1 * DMODEL + n] = v0;
                *(float2*)&out[(size_t)m2 * DMODEL + n] = v1;
            }
        }
    }
}

// ---------------------------------------------------------------------------
// Causal flash-attention-2 on tensor cores.
// grid (16 q-tiles, 64 bh), 256 threads = 8 warps.
// CTA: 128 q-rows; warp w owns rows w*16..+15 (full key width -> in-warp
// softmax). K-tiles of 64 keys streamed through smem (hi/lo + V hi/lo).
// S = Qh*Kh + Qh*Kl + Ql*Kh; PV = Ph*Vh + Ph*Vl + Pl*Vh. P stays in regs.
// Smem rows stride 72 halves -> conflict-free ldmatrix.
// ---------------------------------------------------------------------------
#define KRS 72

__global__ __launch_bounds__(256)
void attn_mma_kernel(const __nv_bfloat16* __restrict__ Qh_,
                     const __nv_bfloat16* __restrict__ Ql_,
                     const __nv_bfloat16* __restrict__ Kh_,
                     const __nv_bfloat16* __restrict__ Kl_,
                     const __nv_bfloat16* __restrict__ Vh_,
                     const __nv_bfloat16* __restrict__ Vl_,
                     float* __restrict__ C)
{
    __shared__ __align__(16) __nv_bfloat16 s0[64 * KRS];  // Qh lo-rows | Kh
    __shared__ __align__(16) __nv_bfloat16 s1[64 * KRS];  // Qh hi-rows | Kl
    __shared__ __align__(16) __nv_bfloat16 s2[64 * KRS];  // Ql lo-rows | Vh
    __shared__ __align__(16) __nv_bfloat16 s3[64 * KRS];  // Ql hi-rows | Vl

    const int tid  = threadIdx.x;
    const int lane = tid & 31;
    const int warp = tid >> 5;
    const int g    = lane >> 2;
    const int t2   = (lane & 3) * 2;
    const int bh   = blockIdx.y;
    const int qt   = (int)gridDim.x - 1 - (int)blockIdx.x;  // longest first
    const int q0   = qt * 128;
    const size_t base = (size_t)bh * SEQ * DK;

    const u32 u0 = (u32)__cvta_generic_to_shared(s0);
    const u32 u1 = (u32)__cvta_generic_to_shared(s1);
    const u32 u2 = (u32)__cvta_generic_to_shared(s2);
    const u32 u3 = (u32)__cvta_generic_to_shared(s3);

    // ---- Stage Q tile (128 x 64, hi+lo) through the 4 smem buffers ----
    #pragma unroll
    for (int q = 0; q < 4; ++q) {
        int idx = tid + q * 256;          // 0..1023
        int row = idx >> 3;               // 0..127
        int c   = (idx & 7) << 3;         // halves
        size_t gq = base + (size_t)(q0 + row) * DK + c;
        int so = (row & 63) * KRS + c;
        if (row < 64) {
            *(uint4*)&s0[so] = *(const uint4*)(Qh_ + gq);
            *(uint4*)&s2[so] = *(const uint4*)(Ql_ + gq);
        } else {
            *(uint4*)&s1[so] = *(const uint4*)(Qh_ + gq);
            *(uint4*)&s3[so] = *(const uint4*)(Ql_ + gq);
        }
    }
    __syncthreads();

    // A-frag lane offsets (validated mapping): tiles {r0/k0, r8/k0, r0/k8, r8/k8}
    const int tr = lane & 7;
    const int aoff = (((lane >> 3) & 1) * 8 + tr) * KRS + ((lane >> 4) & 1) * 8;

    u32 qh[4][4], ql[4][4];
    {
        const int rl = warp * 16;
        const u32 bh_u = (rl < 64) ? u0 : u1;
        const u32 bl_u = (rl < 64) ? u2 : u3;
        const int rbase = (rl & 63) * KRS;
        #pragma unroll
        for (int ks = 0; ks < 4; ++ks) {
            ldm4(qh[ks], bh_u + (u32)(rbase + aoff + ks * 16) * 2);
            ldm4(ql[ks], bl_u + (u32)(rbase + aoff + ks * 16) * 2);
        }
    }
    __syncthreads();   // done with Q staging; buffers become K/V

    // B-frag lane offsets for K (n=keys): tiles {n0/k0, n0/k8, n8/k0, n8/k8}
    int brow[4];
    #pragma unroll
    for (int p = 0; p < 4; ++p)
        brow[p] = (p * 16 + ((lane >> 4) & 1) * 8 + tr) * KRS
                + ((lane >> 3) & 1) * 8;
    // V trans-frag offsets: tiles {k0/d0, k8/d0, k0/d8, k8/d8} (rows = keys)
    const int vt = lane >> 3;
    const int voff = ((vt & 1) * 8 + tr) * KRS + (vt >> 1) * 8;

    float oacc[8][4];
    #pragma unroll
    for (int nf = 0; nf < 8; ++nf)
        #pragma unroll
        for (int r = 0; r < 4; ++r) oacc[nf][r] = 0.0f;
    float m_i[2] = {-1e30f, -1e30f};
    float l_i[2] = {0.0f, 0.0f};

    const int jmax = 2 * qt + 2;
    for (int j = 0; j < jmax; ++j) {
        const int k0 = j * 64;

        // Load K/V tiles (4 arrays x 64 x 64)
        #pragma unroll
        for (int q = 0; q < 2; ++q) {
            int idx = tid + q * 256;      // 0..511
            int row = idx >> 3;
            int c   = (idx & 7) << 3;
            size_t gk = base + (size_t)(k0 + row) * DK + c;
            int so = row * KRS + c;
            *(uint4*)&s0[so] = *(const uint4*)(Kh_ + gk);
            *(uint4*)&s1[so] = *(const uint4*)(Kl_ + gk);
            *(uint4*)&s2[so] = *(const uint4*)(Vh_ + gk);
            *(uint4*)&s3[so] = *(const uint4*)(Vl_ + gk);
        }
        __syncthreads();

        const bool active = (q0 + warp * 16 + 15 >= k0);
        if (active) {
            // ---- S = Q @ K^T (16 x 64 per warp), 3-term split ----
            float sacc[8][4];
            #pragma unroll
            for (int nf = 0; nf < 8; ++nf)
                #pragma unroll
                for (int r = 0; r < 4; ++r) sacc[nf][r] = 0.0f;

            #pragma unroll
            for (int ks = 0; ks < 4; ++ks) {
                const int ko = ks * 16;
                #pragma unroll
                for (int p = 0; p < 4; ++p) {
                    u32 fkh[4], fkl[4];
                    ldm4(fkh, u0 + (u32)(brow[p] + ko) * 2);
                    ldm4(fkl, u1 + (u32)(brow[p] + ko) * 2);
                    mma16816(sacc[2 * p],     qh[ks], fkh[0], fkh[1]);
                    mma16816(sacc[2 * p],     qh[ks], fkl[0], fkl[1]);
                    mma16816(sacc[2 * p],     ql[ks], fkh[0], fkh[1]);
                    mma16816(sacc[2 * p + 1], qh[ks], fkh[2], fkh[3]);
                    mma16816(sacc[2 * p + 1], qh[ks], fkl[2], fkl[3]);
                    mma16816(sacc[2 * p + 1], ql[ks], fkh[2], fkh[3]);
                }
            }

            // Scale + causal mask (only the top two k-tiles intersect diag)
            const int r0 = q0 + warp * 16 + g;
            if (j >= 2 * qt) {
                #pragma unroll
                for (int nf = 0; nf < 8; ++nf) {
                    int col = k0 + nf * 8 + t2;
                    sacc[nf][0] = (col     > r0)     ? -1e30f : sacc[nf][0] * 0.125f;
                    sacc[nf][1] = (col + 1 > r0)     ? -1e30f : sacc[nf][1] * 0.125f;
                    sacc[nf][2] = (col     > r0 + 8) ? -1e30f : sacc[nf][2] * 0.125f;
                    sacc[nf][3] = (col + 1 > r0 + 8) ? -1e30f : sacc[nf][3] * 0.125f;
                }
            } else {
                #pragma unroll
                for (int nf = 0; nf < 8; ++nf)
                    #pragma unroll
                    for (int r = 0; r < 4; ++r) sacc[nf][r] *= 0.125f;
            }

            // ---- online softmax (rows g and g+8; quad-lane reductions) ----
            #pragma unroll
            for (int r = 0; r < 2; ++r) {
                float mt = -1e30f;
                #pragma unroll
                for (int nf = 0; nf < 8; ++nf)
                    mt = fmaxf(mt, fmaxf(sacc[nf][2 * r], sacc[nf][2 * r + 1]));
                mt = fmaxf(mt, __shfl_xor_sync(0xffffffffu, mt, 1));
                mt = fmaxf(mt, __shfl_xor_sync(0xffffffffu, mt, 2));
                float mn = fmaxf(m_i[r], mt);
                float corr = __expf(m_i[r] - mn);
                m_i[r] = mn;
                float rs = 0.0f;
                #pragma unroll
                for (int nf = 0; nf < 8; ++nf) {
                    float p0 = __expf(sacc[nf][2 * r] - mn);
                    float p1 = __expf(sacc[nf][2 * r + 1] - mn);
                    sacc[nf][2 * r] = p0;
                    sacc[nf][2 * r + 1] = p1;
                    rs += p0 + p1;
                    oacc[nf][2 * r] *= corr;
                    oacc[nf][2 * r + 1] *= corr;
                }
                rs += __shfl_xor_sync(0xffffffffu, rs, 1);
                rs += __shfl_xor_sync(0xffffffffu, rs, 2);
                l_i[r] = l_i[r] * corr + rs;
            }

            // ---- O += P @ V, 3-term split (P frags built from sacc) ----
            #pragma unroll
            for (int ks = 0; ks < 4; ++ks) {
                u32 ph[4], pl[4];
                split2(sacc[2 * ks][0], sacc[2 * ks][1], ph[0], pl[0]);
                split2(sacc[2 * ks][2], sacc[2 * ks][3], ph[1], pl[1]);
                split2(sacc[2 * ks + 1][0], sacc[2 * ks + 1][1], ph[2], pl[2]);
                split2(sacc[2 * ks + 1][2], sacc[2 * ks + 1][3], ph[3], pl[3]);
                const int krow = ks * 16;
                #pragma unroll
                for (int p = 0; p < 4; ++p) {
                    u32 fvh[4], fvl[4];
                    u32 va = (u32)((krow * KRS + p * 16 + voff)) * 2;
                    ldm4t(fvh, u2 + va);
                    ldm4t(fvl, u3 + va);
                    mma16816(oacc[2 * p],     ph, fvh[0], fvh[1]);
                    mma16816(oacc[2 * p],     ph, fvl[0], fvl[1]);
                    mma16816(oacc[2 * p],     pl, fvh[0], fvh[1]);
                    mma16816(oacc[2 * p + 1], ph, fvh[2], fvh[3]);
                    mma16816(oacc[2 * p + 1], ph, fvl[2], fvl[3]);
                    mma16816(oacc[2 * p + 1], pl, fvh[2], fvh[3]);
                }
            }
        }
        __syncthreads();   // all warps done reading before next tile load
    }

    // ---- normalize + write ctx [B, L, 1024] ----
    const int b_ = bh >> 4;
    const int h_ = bh & 15;
    const float inv0 = 1.0f / l_i[0];
    const float inv1 = 1.0f / l_i[1];
    const int row0 = q0 + warp * 16 + g;
    #pragma unroll
    for (int nf = 0; nf < 8; ++nf) {
        int d = nf * 8 + t2;
        *(float2*)&C[((size_t)(b_ * SEQ + row0)) * DMODEL + h_ * DK + d] =
            make_float2(oacc[nf][0] * inv0, oacc[nf][1] * inv0);
        *(float2*)&C[((size_t)(b_ * SEQ + row0 + 8)) * DMODEL + h_ * DK + d] =
            make_float2(oacc[nf][2] * inv1, oacc[nf][3] * inv1);
    }
}

// ---------------------------------------------------------------------------
extern "C" void kernel_launch(void* const* d_in, const int* in_sizes, int n_in,
                              void* d_out, int out_size)
{
    (void)in_sizes; (void)n_in; (void)out_size;
    const float* x  = (const float*)d_in[0];
    const float* Wq = (const float*)d_in[2];
    const float* bq = (const float*)d_in[3];
    const float* Wk = (const float*)d_in[4];
    const float* bk = (const float*)d_in[5];
    const float* Wv = (const float*)d_in[6];
    const float* bv = (const float*)d_in[7];
    const float* Wo = (const float*)d_in[8];
    const float* bo = (const float*)d_in[9];
    float* out = (float*)d_out;

    float* Cb;
    __nv_bfloat16 *ah, *al, *wh, *wl, *Qh, *Ql, *Kh, *Kl, *Vh, *Vl;
    cudaGetSymbolAddress((void**)&Cb, g_C);
    cudaGetSymbolAddress((void**)&ah, g_ah);
    cudaGetSymbolAddress((void**)&al, g_al);
    cudaGetSymbolAddress((void**)&wh, g_wh);
    cudaGetSymbolAddress((void**)&wl, g_wl);
    cudaGetSymbolAddress((void**)&Qh, g_Qh);
    cudaGetSymbolAddress((void**)&Ql, g_Ql);
    cudaGetSymbolAddress((void**)&Kh, g_Kh);
    cudaGetSymbolAddress((void**)&Kl, g_Kl);
    cudaGetSymbolAddress((void**)&Vh, g_Vh);
    cudaGetSymbolAddress((void**)&Vl, g_Vl);

    const size_t WSZ = (size_t)DMODEL * DMODEL;
    const int n4 = MROWS * DMODEL / 4;

    split_kernel<<<n4 / 256, 256>>>((const float4*)x, (uint2*)ah, (uint2*)al);
    dim3 wgrid(DMODEL / 32, DMODEL / 32), wblk(32, 8);
    wsplit_kernel<<<wgrid, wblk>>>(Wq, wh + 0 * WSZ, wl + 0 * WSZ);
    wsplit_kernel<<<wgrid, wblk>>>(Wk, wh + 1 * WSZ, wl + 1 * WSZ);
    wsplit_kernel<<<wgrid, wblk>>>(Wv, wh + 2 * WSZ, wl + 2 * WSZ);
    wsplit_kernel<<<wgrid, wblk>>>(Wo, wh + 3 * WSZ, wl + 3 * WSZ);

    dim3 ggrid(DMODEL / 128, MROWS / 128);
    gemm_bf16_split<<<ggrid, 256>>>(ah, al, wh + 0 * WSZ, wl + 0 * WSZ, bq,
                                    nullptr, Qh, Ql, 1);
    gemm_bf16_split<<<ggrid, 256>>>(ah, al, wh + 1 * WSZ, wl + 1 * WSZ, bk,
                                    nullptr, Kh, Kl, 1);
    gemm_bf16_split<<<ggrid, 256>>>(ah, al, wh + 2 * WSZ, wl + 2 * WSZ, bv,
                                    nullptr, Vh, Vl, 1);

    attn_mma_kernel<<<dim3(SEQ / 128, BATCH * NHEADS), 256>>>(
        Qh, Ql, Kh, Kl, Vh, Vl, Cb);

    split_kernel<<<n4 / 256, 256>>>((const float4*)Cb, (uint2*)ah, (uint2*)al);
    gemm_bf16_split<<<ggrid, 256>>>(ah, al, wh + 3 * WSZ, wl + 3 * WSZ, bo,
                                    out, nullptr, nullptr, 0);
}

// round 11
// speedup vs baseline: 2.8676x; 1.0524x over previous
#include <cuda_runtime.h>
#include <cuda_bf16.h>
#include <cstdint>

typedef unsigned int u32;

// ---------------------------------------------------------------------------
// MultiHeadAttention. B=4, L=2048, H=16, d_k=64, d_model=1024, causal.
//   1) split x -> bf16 hi/lo; split+transpose W -> bf16 hi/lo
//   2) Q/K/V projections: split-bf16 MMA GEMM (3-stage cp.async pipeline),
//      epilogue stores Q/K/V as split bf16 hi/lo head-major [B,H,L,64]
//   3) causal flash-attention-2 on tensor cores (2-stage cp.async K/V,
//      3-term split S and PV, fp32 softmax in registers); epilogue writes
//      ctx directly as split bf16 hi/lo [B,L,1024]
//   4) out = split-bf16 GEMM + bo
// ---------------------------------------------------------------------------

#define DMODEL 1024
#define NHEADS 16
#define DK     64
#define BATCH  4
#define SEQ    2048
#define MROWS  (BATCH * SEQ)   // 8192

__device__ __align__(16) __nv_bfloat16 g_ah[(size_t)MROWS * DMODEL];  // x / ctx hi
__device__ __align__(16) __nv_bfloat16 g_al[(size_t)MROWS * DMODEL];  // x / ctx lo
__device__ __align__(16) __nv_bfloat16 g_wh[4][(size_t)DMODEL * DMODEL];
__device__ __align__(16) __nv_bfloat16 g_wl[4][(size_t)DMODEL * DMODEL];
#define QKV_ELEMS ((size_t)BATCH * NHEADS * SEQ * DK)
__device__ __align__(16) __nv_bfloat16 g_Qh[QKV_ELEMS];
__device__ __align__(16) __nv_bfloat16 g_Ql[QKV_ELEMS];
__device__ __align__(16) __nv_bfloat16 g_Kh[QKV_ELEMS];
__device__ __align__(16) __nv_bfloat16 g_Kl[QKV_ELEMS];
__device__ __align__(16) __nv_bfloat16 g_Vh[QKV_ELEMS];
__device__ __align__(16) __nv_bfloat16 g_Vl[QKV_ELEMS];

extern __shared__ __nv_bfloat16 dynsm[];

// ---------------------------------------------------------------------------
// PTX wrappers (ldm4/ldm4t/mma16816 validated in R9/R10).
// ---------------------------------------------------------------------------
__device__ __forceinline__ void ldm4(u32 (&r)[4], u32 addr)
{
    asm volatile("ldmatrix.sync.aligned.m8n8.x4.shared.b16 {%0,%1,%2,%3}, [%4];"
                 : "=r"(r[0]), "=r"(r[1]), "=r"(r[2]), "=r"(r[3])
                 : "r"(addr));
}

__device__ __forceinline__ void ldm4t(u32 (&r)[4], u32 addr)
{
    asm volatile("ldmatrix.sync.aligned.m8n8.x4.trans.shared.b16 {%0,%1,%2,%3}, [%4];"
                 : "=r"(r[0]), "=r"(r[1]), "=r"(r[2]), "=r"(r[3])
                 : "r"(addr));
}

__device__ __forceinline__ void mma16816(float (&d)[4], const u32 (&a)[4],
                                         u32 b0, u32 b1)
{
    asm volatile("mma.sync.aligned.m16n8k16.row.col.f32.bf16.bf16.f32 "
                 "{%0,%1,%2,%3},{%4,%5,%6,%7},{%8,%9},{%0,%1,%2,%3};"
                 : "+f"(d[0]), "+f"(d[1]), "+f"(d[2]), "+f"(d[3])
                 : "r"(a[0]), "r"(a[1]), "r"(a[2]), "r"(a[3]),
                   "r"(b0), "r"(b1));
}

__device__ __forceinline__ void cpasync16(u32 saddr, const void* gaddr)
{
    asm volatile("cp.async.cg.shared.global [%0], [%1], 16;"
                 :: "r"(saddr), "l"(gaddr));
}
__device__ __forceinline__ void cpcommit()
{
    asm volatile("cp.async.commit_group;");
}
template<int N> __device__ __forceinline__ void cpwait()
{
    asm volatile("cp.async.wait_group %0;" :: "n"(N));
}

__device__ __forceinline__ void split2(float a, float b, u32& hi, u32& lo)
{
    __nv_bfloat16 ha = __float2bfloat16(a), hb = __float2bfloat16(b);
    __nv_bfloat16 la = __float2bfloat16(a - __bfloat162float(ha));
    __nv_bfloat16 lb = __float2bfloat16(b - __bfloat162float(hb));
    union { __nv_bfloat162 v; u32 u; } H, L;
    H.v.x = ha; H.v.y = hb; L.v.x = la; L.v.y = lb;
    hi = H.u; lo = L.u;
}

// ---------------------------------------------------------------------------
// fp32 -> (bf16 hi, lo) split; and W transpose+split (unchanged, ~25us total).
// ---------------------------------------------------------------------------
union Pack4 { __nv_bfloat16 b[4]; uint2 u; };

__global__ void split_kernel(const float4* __restrict__ src,
                             uint2* __restrict__ hi, uint2* __restrict__ lo)
{
    int i = blockIdx.x * blockDim.x + threadIdx.x;
    float4 v = src[i];
    float vv[4] = {v.x, v.y, v.z, v.w};
    Pack4 H, L;
    #pragma unroll
    for (int j = 0; j < 4; ++j) {
        __nv_bfloat16 h = __float2bfloat16(vv[j]);
        H.b[j] = h;
        L.b[j] = __float2bfloat16(vv[j] - __bfloat162float(h));
    }
    hi[i] = H.u;
    lo[i] = L.u;
}

__global__ void wsplit_kernel(const float* __restrict__ W,
                              __nv_bfloat16* __restrict__ th,
                              __nv_bfloat16* __restrict__ tl)
{
    __shared__ float t[32][33];
    const int tx = threadIdx.x, ty = threadIdx.y;
    const int bx = blockIdx.x * 32, by = blockIdx.y * 32;
    #pragma unroll
    for (int i = 0; i < 32; i += 8)
        t[ty + i][tx] = W[(size_t)(by + ty + i) * DMODEL + bx + tx];
    __syncthreads();
    #pragma unroll
    for (int i = 0; i < 32; i += 8) {
        float v = t[tx][ty + i];
        int n = bx + ty + i, k = by + tx;
        __nv_bfloat16 h = __float2bfloat16(v);
        th[(size_t)n * DMODEL + k] = h;
        tl[(size_t)n * DMODEL + k] = __float2bfloat16(v - __bfloat162float(h));
    }
}

// ---------------------------------------------------------------------------
// Split-bf16 GEMM, 3-stage cp.async pipeline.
// BM=128, BN=128, BK=32; 256 threads = 8 warps (4m x 2n), warp tile 32x64.
// Stage = {A_h, A_l, B_h, B_l} each 128x40 halves; 3 stages = 122880 B smem.
// One __syncthreads per k-chunk; loads for chunk kc+2 run as DMA behind MMAs.
// ---------------------------------------------------------------------------
#define STG (4 * 128 * 40)          // halves per stage
#define GEMM_SMEM (3 * STG * 2)     // bytes

__global__ __launch_bounds__(256)
void gemm_bf16_split(const __nv_bfloat16* __restrict__ Ah,
                     const __nv_bfloat16* __restrict__ Al,
                     const __nv_bfloat16* __restrict__ Bh,
                     const __nv_bfloat16* __restrict__ Bl,
                     const float* __restrict__ bias,
                     float* __restrict__ out,
                     __nv_bfloat16* __restrict__ oH,
                     __nv_bfloat16* __restrict__ oL, int mode)
{
    const int tid  = threadIdx.x;
    const int lane = tid & 31;
    const int warp = tid >> 5;
    const int wm   = warp >> 1;
    const int wn   = warp & 1;
    const int m0   = blockIdx.y * 128;
    const int n0   = blockIdx.x * 128;

    const int rb = tid >> 2;          // 0..63
    const int c8 = (tid & 3) << 3;    // halves

    const u32 smb = (u32)__cvta_generic_to_shared(dynsm);

    const int tr = lane & 7;
    const int arow = (wm * 32 + ((lane >> 3) & 1) * 8 + tr) * 40
                   + ((lane >> 4) & 1) * 8;
    int brow[4];
    #pragma unroll
    for (int p = 0; p < 4; ++p)
        brow[p] = (wn * 64 + p * 16 + ((lane >> 4) & 1) * 8 + tr) * 40
                + ((lane >> 3) & 1) * 8;

    float acc[2][8][4];
    #pragma unroll
    for (int mi = 0; mi < 2; ++mi)
        #pragma unroll
        for (int ni = 0; ni < 8; ++ni)
            #pragma unroll
            for (int r = 0; r < 4; ++r) acc[mi][ni][r] = 0.0f;

#define CP_CHUNK(slot, k0) do {                                             \
    u32 sb_ = smb + (u32)((slot) * STG) * 2;                                \
    _Pragma("unroll")                                                       \
    for (int q = 0; q < 2; ++q) {                                           \
        int row = rb + 64 * q;                                              \
        size_t ga = (size_t)(m0 + row) * DMODEL + (k0) + c8;                \
        size_t gb = (size_t)(n0 + row) * DMODEL + (k0) + c8;                \
        u32 so = (u32)(row * 40 + c8) * 2;                                  \
        cpasync16(sb_ + so,                  Ah + ga);                      \
        cpasync16(sb_ + 128 * 80 + so,      Al + ga);                       \
        cpasync16(sb_ + 2 * 128 * 80 + so,  Bh + gb);                       \
        cpasync16(sb_ + 3 * 128 * 80 + so,  Bl + gb);                       \
    } } while (0)

    CP_CHUNK(0, 0);  cpcommit();
    CP_CHUNK(1, 32); cpcommit();

    const int NK = DMODEL / 32;   // 32
    for (int kc = 0; kc < NK; ++kc) {
        cpwait<1>();
        __syncthreads();           // stage kc%3 visible; slot (kc+2)%3 free
        if (kc + 2 < NK) CP_CHUNK((kc + 2) % 3, (kc + 2) * 32);
        cpcommit();                // unconditional: keeps group indices uniform

        const u32 sb0 = smb + (u32)((kc % 3) * STG) * 2;
        const u32 sa_h = sb0;
        const u32 sa_l = sb0 + 128 * 80;
        const u32 sb_h = sb0 + 2 * 128 * 80;
        const u32 sb_l = sb0 + 3 * 128 * 80;

        #pragma unroll
        for (int ks = 0; ks < 2; ++ks) {
            const int ko = ks * 16;
            u32 fa_h0[4], fa_h1[4], fa_l0[4], fa_l1[4];
            ldm4(fa_h0, sa_h + (u32)(arow + ko) * 2);
            ldm4(fa_h1, sa_h + (u32)(arow + 640 + ko) * 2);
            ldm4(fa_l0, sa_l + (u32)(arow + ko) * 2);
            ldm4(fa_l1, sa_l + (u32)(arow + 640 + ko) * 2);
            #pragma unroll
            for (int p = 0; p < 4; ++p) {
                u32 fbh[4], fbl[4];
                ldm4(fbh, sb_h + (u32)(brow[p] + ko) * 2);
                ldm4(fbl, sb_l + (u32)(brow[p] + ko) * 2);
                mma16816(acc[0][2 * p],     fa_h0, fbh[0], fbh[1]);
                mma16816(acc[0][2 * p],     fa_h0, fbl[0], fbl[1]);
                mma16816(acc[0][2 * p],     fa_l0, fbh[0], fbh[1]);
                mma16816(acc[0][2 * p + 1], fa_h0, fbh[2], fbh[3]);
                mma16816(acc[0][2 * p + 1], fa_h0, fbl[2], fbl[3]);
                mma16816(acc[0][2 * p + 1], fa_l0, fbh[2], fbh[3]);
                mma16816(acc[1][2 * p],     fa_h1, fbh[0], fbh[1]);
                mma16816(acc[1][2 * p],     fa_h1, fbl[0], fbl[1]);
                mma16816(acc[1][2 * p],     fa_l1, fbh[0], fbh[1]);
                mma16816(acc[1][2 * p + 1], fa_h1, fbh[2], fbh[3]);
                mma16816(acc[1][2 * p + 1], fa_h1, fbl[2], fbl[3]);
                mma16816(acc[1][2 * p + 1], fa_l1, fbh[2], fbh[3]);
            }
        }
    }
#undef CP_CHUNK

    const int g  = lane >> 2;
    const int t2 = (lane & 3) * 2;
    #pragma unroll
    for (int mi = 0; mi < 2; ++mi) {
        #pragma unroll
        for (int ni = 0; ni < 8; ++ni) {
            int n = n0 + wn * 64 + ni * 8 + t2;
            float2 bb = *(const float2*)&bias[n];
            int m1 = m0 + wm * 32 + mi * 16 + g;
            int m2 = m1 + 8;
            float2 v0 = make_float2(acc[mi][ni][0] + bb.x, acc[mi][ni][1] + bb.y);
            float2 v1 = make_float2(acc[mi][ni][2] + bb.x, acc[mi][ni][3] + bb.y);
            if (mode == 1) {
                int h_ = n >> 6, d_ = n & (DK - 1);
                int b1 = m1 >> 11, l1 = m1 & (SEQ - 1);
                int b2 = m2 >> 11, l2 = m2 & (SEQ - 1);
                size_t i1 = (((size_t)(b1 * NHEADS + h_) * SEQ + l1) << 6) + d_;
                size_t i2 = (((size_t)(b2 * NHEADS + h_) * SEQ + l2) << 6) + d_;
                u32 h0, l0, h1, l1p;
                split2(v0.x, v0.y, h0, l0);
                split2(v1.x, v1.y, h1, l1p);
                *(u32*)&oH[i1] = h0; *(u32*)&oL[i1] = l0;
                *(u32*)&oH[i2] = h1; *(u32*)&oL[i2] = l1p;
            } else {
                *(float2*)&out[(size_t)m1 * DMODEL + n] = v0;
                *(float2*)&out[(size_t)m2 * DMODEL + n] = v1;
            }
        }
    }
}

// ---------------------------------------------------------------------------
// Causal flash-attention-2, tensor cores, 2-stage cp.async K/V pipeline.
// grid (16 q-tiles, 64 bh), 256 threads = 8 warps; warp owns 16 q-rows.
// Stage = {Kh, Kl, Vh, Vl} each 64x72 halves; 2 stages = 73728 B smem.
// Epilogue writes ctx as split bf16 hi/lo directly.
// ---------------------------------------------------------------------------
#define KRS 72
#define ASTG (4 * 64 * KRS)          // halves per stage
#define ATTN_SMEM (2 * ASTG * 2)     // bytes

__global__ __launch_bounds__(256)
void attn_mma_kernel(const __nv_bfloat16* __restrict__ Qh_,
                     const __nv_bfloat16* __restrict__ Ql_,
                     const __nv_bfloat16* __restrict__ Kh_,
                     const __nv_bfloat16* __restrict__ Kl_,
                     const __nv_bfloat16* __restrict__ Vh_,
                     const __nv_bfloat16* __restrict__ Vl_,
                     __nv_bfloat16* __restrict__ Ch,
                     __nv_bfloat16* __restrict__ Cl)
{
    const int tid  = threadIdx.x;
    const int lane = tid & 31;
    const int warp = tid >> 5;
    const int g    = lane >> 2;
    const int t2   = (lane & 3) * 2;
    const int bh   = blockIdx.y;
    const int qt   = (int)gridDim.x - 1 - (int)blockIdx.x;  // longest first
    const int q0   = qt * 128;
    const size_t base = (size_t)bh * SEQ * DK;

    const u32 smb = (u32)__cvta_generic_to_shared(dynsm);
    const u32 A0 = smb;                       // stage0: Kh | Q staging
    const u32 A1 = smb + (u32)(64 * KRS) * 2;
    const u32 A2 = smb + (u32)(2 * 64 * KRS) * 2;
    const u32 A3 = smb + (u32)(3 * 64 * KRS) * 2;

    // ---- Stage Q tile (128 x 64, hi+lo) via stage-0 buffers ----
    #pragma unroll
    for (int q = 0; q < 4; ++q) {
        int idx = tid + q * 256;
        int row = idx >> 3;
        int c   = (idx & 7) << 3;
        size_t gq = base + (size_t)(q0 + row) * DK + c;
        u32 so = (u32)((row & 63) * KRS + c) * 2;
        if (row < 64) {
            *(uint4*)(dynsm + ((so >> 1)))                 = *(const uint4*)(Qh_ + gq);
            *(uint4*)(dynsm + (2 * 64 * KRS) + (so >> 1))  = *(const uint4*)(Ql_ + gq);
        } else {
            *(uint4*)(dynsm + (64 * KRS) + (so >> 1))      = *(const uint4*)(Qh_ + gq);
            *(uint4*)(dynsm + (3 * 64 * KRS) + (so >> 1))  = *(const uint4*)(Ql_ + gq);
        }
    }
    __syncthreads();

    const int tr = lane & 7;
    const int aoff = (((lane >> 3) & 1) * 8 + tr) * KRS + ((lane >> 4) & 1) * 8;

    u32 qh[4][4], ql[4][4];
    {
        const int rl = warp * 16;
        const u32 bh_u = (rl < 64) ? A0 : A1;
        const u32 bl_u = (rl < 64) ? A2 : A3;
        const int rbase = (rl & 63) * KRS;
        #pragma unroll
        for (int ks = 0; ks < 4; ++ks) {
            ldm4(qh[ks], bh_u + (u32)(rbase + aoff + ks * 16) * 2);
            ldm4(ql[ks], bl_u + (u32)(rbase + aoff + ks * 16) * 2);
        }
    }
    __syncthreads();   // Q consumed; buffers become the K/V pipeline

    // cp.async K/V tile loader: 512 uint4 per array; 2 per thread per array.
#define CP_KV(slot, k0) do {                                                \
    u32 sb_ = smb + (u32)((slot) * ASTG) * 2;                               \
    _Pragma("unroll")                                                       \
    for (int q = 0; q < 2; ++q) {                                           \
        int idx = tid + q * 256;                                            \
        int row = idx >> 3;                                                 \
        int c   = (idx & 7) << 3;                                           \
        size_t gk = base + (size_t)((k0) + row) * DK + c;                   \
        u32 so = (u32)(row * KRS + c) * 2;                                  \
        cpasync16(sb_ + so,                    Kh_ + gk);                   \
        cpasync16(sb_ + (u32)(64*KRS)*2 + so,  Kl_ + gk);                   \
        cpasync16(sb_ + (u32)(2*64*KRS)*2 + so, Vh_ + gk);                  \
        cpasync16(sb_ + (u32)(3*64*KRS)*2 + so, Vl_ + gk);                  \
    } } while (0)

    int brow[4];
    #pragma unroll
    for (int p = 0; p < 4; ++p)
        brow[p] = (p * 16 + ((lane >> 4) & 1) * 8 + tr) * KRS
                + ((lane >> 3) & 1) * 8;
    const int vt = lane >> 3;
    const int voff = ((vt & 1) * 8 + tr) * KRS + (vt >> 1) * 8;

    float oacc[8][4];
    #pragma unroll
    for (int nf = 0; nf < 8; ++nf)
        #pragma unroll
        for (int r = 0; r < 4; ++r) oacc[nf][r] = 0.0f;
    float m_i[2] = {-1e30f, -1e30f};
    float l_i[2] = {0.0f, 0.0f};

    const int jmax = 2 * qt + 2;
    CP_KV(0, 0); cpcommit();

    for (int j = 0; j < jmax; ++j) {
        if (j + 1 < jmax) CP_KV((j + 1) & 1, (j + 1) * 64);
        cpcommit();
        cpwait<1>();
        __syncthreads();           // tile j visible in slot j&1

        const u32 sb0 = smb + (u32)((j & 1) * ASTG) * 2;
        const u32 uK_h = sb0;
        const u32 uK_l = sb0 + (u32)(64 * KRS) * 2;
        const u32 uV_h = sb0 + (u32)(2 * 64 * KRS) * 2;
        const u32 uV_l = sb0 + (u32)(3 * 64 * KRS) * 2;
        const int k0 = j * 64;

        const bool active = (q0 + warp * 16 + 15 >= k0);
        if (active) {
            float sacc[8][4];
            #pragma unroll
            for (int nf = 0; nf < 8; ++nf)
                #pragma unroll
                for (int r = 0; r < 4; ++r) sacc[nf][r] = 0.0f;

            #pragma unroll
            for (int ks = 0; ks < 4; ++ks) {
                const int ko = ks * 16;
                #pragma unroll
                for (int p = 0; p < 4; ++p) {
                    u32 fkh[4], fkl[4];
                    ldm4(fkh, uK_h + (u32)(brow[p] + ko) * 2);
                    ldm4(fkl, uK_l + (u32)(brow[p] + ko) * 2);
                    mma16816(sacc[2 * p],     qh[ks], fkh[0], fkh[1]);
                    mma16816(sacc[2 * p],     qh[ks], fkl[0], fkl[1]);
                    mma16816(sacc[2 * p],     ql[ks], fkh[0], fkh[1]);
                    mma16816(sacc[2 * p + 1], qh[ks], fkh[2], fkh[3]);
                    mma16816(sacc[2 * p + 1], qh[ks], fkl[2], fkl[3]);
                    mma16816(sacc[2 * p + 1], ql[ks], fkh[2], fkh[3]);
                }
            }

            const int r0 = q0 + warp * 16 + g;
            if (j >= 2 * qt) {
                #pragma unroll
                for (int nf = 0; nf < 8; ++nf) {
                    int col = k0 + nf * 8 + t2;
                    sacc[nf][0] = (col     > r0)     ? -1e30f : sacc[nf][0] * 0.125f;
                    sacc[nf][1] = (col + 1 > r0)     ? -1e30f : sacc[nf][1] * 0.125f;
                    sacc[nf][2] = (col     > r0 + 8) ? -1e30f : sacc[nf][2] * 0.125f;
                    sacc[nf][3] = (col + 1 > r0 + 8) ? -1e30f : sacc[nf][3] * 0.125f;
                }
            } else {
                #pragma unroll
                for (int nf = 0; nf < 8; ++nf)
                    #pragma unroll
                    for (int r = 0; r < 4; ++r) sacc[nf][r] *= 0.125f;
            }

            #pragma unroll
            for (int r = 0; r < 2; ++r) {
                float mt = -1e30f;
                #pragma unroll
                for (int nf = 0; nf < 8; ++nf)
                    mt = fmaxf(mt, fmaxf(sacc[nf][2 * r], sacc[nf][2 * r + 1]));
                mt = fmaxf(mt, __shfl_xor_sync(0xffffffffu, mt, 1));
                mt = fmaxf(mt, __shfl_xor_sync(0xffffffffu, mt, 2));
                float mn = fmaxf(m_i[r], mt);
                float corr = __expf(m_i[r] - mn);
                m_i[r] = mn;
                float rs = 0.0f;
                #pragma unroll
                for (int nf = 0; nf < 8; ++nf) {
                    float p0 = __expf(sacc[nf][2 * r] - mn);
                    float p1 = __expf(sacc[nf][2 * r + 1] - mn);
                    sacc[nf][2 * r] = p0;
                    sacc[nf][2 * r + 1] = p1;
                    rs += p0 + p1;
                    oacc[nf][2 * r] *= corr;
                    oacc[nf][2 * r + 1] *= corr;
                }
                rs += __shfl_xor_sync(0xffffffffu, rs, 1);
                rs += __shfl_xor_sync(0xffffffffu, rs, 2);
                l_i[r] = l_i[r] * corr + rs;
            }

            #pragma unroll
            for (int ks = 0; ks < 4; ++ks) {
                u32 ph[4], pl[4];
                split2(sacc[2 * ks][0], sacc[2 * ks][1], ph[0], pl[0]);
                split2(sacc[2 * ks][2], sacc[2 * ks][3], ph[1], pl[1]);
                split2(sacc[2 * ks + 1][0], sacc[2 * ks + 1][1], ph[2], pl[2]);
                split2(sacc[2 * ks + 1][2], sacc[2 * ks + 1][3], ph[3], pl[3]);
                const int krow = ks * 16;
                #pragma unroll
                for (int p = 0; p < 4; ++p) {
                    u32 fvh[4], fvl[4];
                    u32 va = (u32)((krow * KRS + p * 16 + voff)) * 2;
                    ldm4t(fvh, uV_h + va);
                    ldm4t(fvl, uV_l + va);
                    mma16816(oacc[2 * p],     ph, fvh[0], fvh[1]);
                    mma16816(oacc[2 * p],     ph, fvl[0], fvl[1]);
                    mma16816(oacc[2 * p],     pl, fvh[0], fvh[1]);
                    mma16816(oacc[2 * p + 1], ph, fvh[2], fvh[3]);
                    mma16816(oacc[2 * p + 1], ph, fvl[2], fvl[3]);
                    mma16816(oacc[2 * p + 1], pl, fvh[2], fvh[3]);
                }
            }
        }
        __syncthreads();   // all warps done reading slot j&1 before overwrite
    }
#undef CP_KV

    // ---- normalize + write ctx as split bf16 [B, L, 1024] ----
    const int b_ = bh >> 4;
    const int h_ = bh & 15;
    const float inv0 = 1.0f / l_i[0];
    const float inv1 = 1.0f / l_i[1];
    const int row0 = q0 + warp * 16 + g;
    #pragma unroll
    for (int nf = 0; nf < 8; ++nf) {
        int d = nf * 8 + t2;
        size_t i0 = ((size_t)(b_ * SEQ + row0)) * DMODEL + h_ * DK + d;
        size_t i1 = ((size_t)(b_ * SEQ + row0 + 8)) * DMODEL + h_ * DK + d;
        u32 h0, l0, h1, l1;
        split2(oacc[nf][0] * inv0, oacc[nf][1] * inv0, h0, l0);
        split2(oacc[nf][2] * inv1, oacc[nf][3] * inv1, h1, l1);
        *(u32*)&Ch[i0] = h0; *(u32*)&Cl[i0] = l0;
        *(u32*)&Ch[i1] = h1; *(u32*)&Cl[i1] = l1;
    }
}

// ---------------------------------------------------------------------------
extern "C" void kernel_launch(void* const* d_in, const int* in_sizes, int n_in,
                              void* d_out, int out_size)
{
    (void)in_sizes; (void)n_in; (void)out_size;
    const float* x  = (const float*)d_in[0];
    const float* Wq = (const float*)d_in[2];
    const float* bq = (const float*)d_in[3];
    const float* Wk = (const float*)d_in[4];
    const float* bk = (const float*)d_in[5];
    const float* Wv = (const float*)d_in[6];
    const float* bv = (const float*)d_in[7];
    const float* Wo = (const float*)d_in[8];
    const float* bo = (const float*)d_in[9];
    float* out = (float*)d_out;

    __nv_bfloat16 *ah, *al, *wh, *wl, *Qh, *Ql, *Kh, *Kl, *Vh, *Vl;
    cudaGetSymbolAddress((void**)&ah, g_ah);
    cudaGetSymbolAddress((void**)&al, g_al);
    cudaGetSymbolAddress((void**)&wh, g_wh);
    cudaGetSymbolAddress((void**)&wl, g_wl);
    cudaGetSymbolAddress((void**)&Qh, g_Qh);
    cudaGetSymbolAddress((void**)&Ql, g_Ql);
    cudaGetSymbolAddress((void**)&Kh, g_Kh);
    cudaGetSymbolAddress((void**)&Kl, g_Kl);
    cudaGetSymbolAddress((void**)&Vh, g_Vh);
    cudaGetSymbolAddress((void**)&Vl, g_Vl);

    cudaFuncSetAttribute(gemm_bf16_split,
                         cudaFuncAttributeMaxDynamicSharedMemorySize, GEMM_SMEM);
    cudaFuncSetAttribute(attn_mma_kernel,
                         cudaFuncAttributeMaxDynamicSharedMemorySize, ATTN_SMEM);

    const size_t WSZ = (size_t)DMODEL * DMODEL;
    const int n4 = MROWS * DMODEL / 4;

    split_kernel<<<n4 / 256, 256>>>((const float4*)x, (uint2*)ah, (uint2*)al);
    dim3 wgrid(DMODEL / 32, DMODEL / 32), wblk(32, 8);
    wsplit_kernel<<<wgrid, wblk>>>(Wq, wh + 0 * WSZ, wl + 0 * WSZ);
    wsplit_kernel<<<wgrid, wblk>>>(Wk, wh + 1 * WSZ, wl + 1 * WSZ);
    wsplit_kernel<<<wgrid, wblk>>>(Wv, wh + 2 * WSZ, wl + 2 * WSZ);
    wsplit_kernel<<<wgrid, wblk>>>(Wo, wh + 3 * WSZ, wl + 3 * WSZ);

    dim3 ggrid(DMODEL / 128, MROWS / 128);
    gemm_bf16_split<<<ggrid, 256, GEMM_SMEM>>>(ah, al, wh + 0 * WSZ, wl + 0 * WSZ,
                                               bq, nullptr, Qh, Ql, 1);
    gemm_bf16_split<<<ggrid, 256, GEMM_SMEM>>>(ah, al, wh + 1 * WSZ, wl + 1 * WSZ,
                                               bk, nullptr, Kh, Kl, 1);
    gemm_bf16_split<<<ggrid, 256, GEMM_SMEM>>>(ah, al, wh + 2 * WSZ, wl + 2 * WSZ,
                                               bv, nullptr, Vh, Vl, 1);

    // attention writes ctx (split bf16) directly into ah/al
    attn_mma_kernel<<<dim3(SEQ / 128, BATCH * NHEADS), 256, ATTN_SMEM>>>(
        Qh, Ql, Kh, Kl, Vh, Vl, ah, al);

    gemm_bf16_split<<<ggrid, 256, GEMM_SMEM>>>(ah, al, wh + 3 * WSZ, wl + 3 * WSZ,
                                               bo, out, nullptr, nullptr, 0);
}

// round 13
// speedup vs baseline: 3.7155x; 1.2957x over previous
#include <cuda_runtime.h>
#include <cuda_bf16.h>
#include <cuda_fp16.h>
#include <cstdint>

typedef unsigned int u32;
typedef unsigned short u16;

// ---------------------------------------------------------------------------
// MultiHeadAttention. B=4, L=2048, H=16, d_k=64, d_model=1024, causal.
// mma.sync roofline (~273 TF/s bf16) established in R11; tcgen05 blocked by
// harness PTX target (compute_103, no 'a'). This round reduces MMA volume:
//   - Q/K projections + S=QK^T: 3-term split-bf16 (accuracy for logits)
//   - V projection, P@V, out projection: 2-term fp16 (one operand single,
//     other dual; error ~2.8e-4/stage, linear paths only)
//   - Q and K projection GEMMs fused into one launch (gridDim.z=2)
// ---------------------------------------------------------------------------

#define DMODEL 1024
#define NHEADS 16
#define DK     64
#define BATCH  4
#define SEQ    2048
#define MROWS  (BATCH * SEQ)   // 8192

__device__ __align__(16) __nv_bfloat16 g_ah[(size_t)MROWS * DMODEL];   // x hi (bf16)
__device__ __align__(16) __nv_bfloat16 g_al[(size_t)MROWS * DMODEL];   // x lo (bf16)
__device__ __align__(16) __half        g_af[(size_t)MROWS * DMODEL];   // x / ctx (fp16)
__device__ __align__(16) u16 g_wh[4][(size_t)DMODEL * DMODEL];  // W^T hi (bf16|fp16 bits)
__device__ __align__(16) u16 g_wl[4][(size_t)DMODEL * DMODEL];  // W^T lo
#define QKV_ELEMS ((size_t)BATCH * NHEADS * SEQ * DK)
__device__ __align__(16) __nv_bfloat16 g_Qh[QKV_ELEMS];
__device__ __align__(16) __nv_bfloat16 g_Ql[QKV_ELEMS];
__device__ __align__(16) __nv_bfloat16 g_Kh[QKV_ELEMS];
__device__ __align__(16) __nv_bfloat16 g_Kl[QKV_ELEMS];
__device__ __align__(16) __half        g_Vh[QKV_ELEMS];   // V dual fp16
__device__ __align__(16) __half        g_Vl[QKV_ELEMS];

extern __shared__ __nv_bfloat16 dynsm[];

// ---------------------------------------------------------------------------
// PTX wrappers (ldm4/ldm4t/mma16816 validated R9-R11).
// ---------------------------------------------------------------------------
__device__ __forceinline__ void ldm4(u32 (&r)[4], u32 addr)
{
    asm volatile("ldmatrix.sync.aligned.m8n8.x4.shared.b16 {%0,%1,%2,%3}, [%4];"
                 : "=r"(r[0]), "=r"(r[1]), "=r"(r[2]), "=r"(r[3])
                 : "r"(addr));
}

__device__ __forceinline__ void ldm4t(u32 (&r)[4], u32 addr)
{
    asm volatile("ldmatrix.sync.aligned.m8n8.x4.trans.shared.b16 {%0,%1,%2,%3}, [%4];"
                 : "=r"(r[0]), "=r"(r[1]), "=r"(r[2]), "=r"(r[3])
                 : "r"(addr));
}

__device__ __forceinline__ void mma16816(float (&d)[4], const u32 (&a)[4],
                                         u32 b0, u32 b1)
{
    asm volatile("mma.sync.aligned.m16n8k16.row.col.f32.bf16.bf16.f32 "
                 "{%0,%1,%2,%3},{%4,%5,%6,%7},{%8,%9},{%0,%1,%2,%3};"
                 : "+f"(d[0]), "+f"(d[1]), "+f"(d[2]), "+f"(d[3])
                 : "r"(a[0]), "r"(a[1]), "r"(a[2]), "r"(a[3]),
                   "r"(b0), "r"(b1));
}

__device__ __forceinline__ void mma16816h(float (&d)[4], const u32 (&a)[4],
                                          u32 b0, u32 b1)
{
    asm volatile("mma.sync.aligned.m16n8k16.row.col.f32.f16.f16.f32 "
                 "{%0,%1,%2,%3},{%4,%5,%6,%7},{%8,%9},{%0,%1,%2,%3};"
                 : "+f"(d[0]), "+f"(d[1]), "+f"(d[2]), "+f"(d[3])
                 : "r"(a[0]), "r"(a[1]), "r"(a[2]), "r"(a[3]),
                   "r"(b0), "r"(b1));
}

__device__ __forceinline__ void cpasync16(u32 saddr, const void* gaddr)
{
    asm volatile("cp.async.cg.shared.global [%0], [%1], 16;"
                 :: "r"(saddr), "l"(gaddr));
}
__device__ __forceinline__ void cpcommit()
{
    asm volatile("cp.async.commit_group;");
}
template<int N> __device__ __forceinline__ void cpwait()
{
    asm volatile("cp.async.wait_group %0;" :: "n"(N));
}

__device__ __forceinline__ void split2(float a, float b, u32& hi, u32& lo)
{
    __nv_bfloat16 ha = __float2bfloat16(a), hb = __float2bfloat16(b);
    __nv_bfloat16 la = __float2bfloat16(a - __bfloat162float(ha));
    __nv_bfloat16 lb = __float2bfloat16(b - __bfloat162float(hb));
    union { __nv_bfloat162 v; u32 u; } H, L;
    H.v.x = ha; H.v.y = hb; L.v.x = la; L.v.y = lb;
    hi = H.u; lo = L.u;
}

__device__ __forceinline__ void split2h(float a, float b, u32& hi, u32& lo)
{
    __half ha = __float2half_rn(a), hb = __float2half_rn(b);
    __half la = __float2half_rn(a - __half2float(ha));
    __half lb = __float2half_rn(b - __half2float(hb));
    union { __half2 v; u32 u; } H, L;
    H.v.x = ha; H.v.y = hb; L.v.x = la; L.v.y = lb;
    hi = H.u; lo = L.u;
}

__device__ __forceinline__ u32 packh2(float a, float b)
{
    union { __half2 v; u32 u; } P;
    P.v = __floats2half2_rn(a, b);
    return P.u;
}

// ---------------------------------------------------------------------------
// fp32 -> bf16 hi/lo + fp16 single, 4 elems/thread.
// ---------------------------------------------------------------------------
union Pack4 { __nv_bfloat16 b[4]; uint2 u; };

__global__ void split_kernel(const float4* __restrict__ src,
                             uint2* __restrict__ hi, uint2* __restrict__ lo,
                             uint2* __restrict__ f16o)
{
    int i = blockIdx.x * blockDim.x + threadIdx.x;
    float4 v = src[i];
    float vv[4] = {v.x, v.y, v.z, v.w};
    Pack4 H, L;
    #pragma unroll
    for (int j = 0; j < 4; ++j) {
        __nv_bfloat16 h = __float2bfloat16(vv[j]);
        H.b[j] = h;
        L.b[j] = __float2bfloat16(vv[j] - __bfloat162float(h));
    }
    hi[i] = H.u;
    lo[i] = L.u;
    uint2 F;
    F.x = packh2(vv[0], vv[1]);
    F.y = packh2(vv[2], vv[3]);
    f16o[i] = F;
}

// W [K,N] fp32 -> W^T [N,K] hi/lo; f16flag selects fp16 vs bf16 bits.
__global__ void wsplit_kernel(const float* __restrict__ W,
                              u16* __restrict__ th, u16* __restrict__ tl,
                              int f16flag)
{
    __shared__ float t[32][33];
    const int tx = threadIdx.x, ty = threadIdx.y;
    const int bx = blockIdx.x * 32, by = blockIdx.y * 32;
    #pragma unroll
    for (int i = 0; i < 32; i += 8)
        t[ty + i][tx] = W[(size_t)(by + ty + i) * DMODEL + bx + tx];
    __syncthreads();
    #pragma unroll
    for (int i = 0; i < 32; i += 8) {
        float v = t[tx][ty + i];
        int n = bx + ty + i, k = by + tx;
        size_t o = (size_t)n * DMODEL + k;
        if (f16flag) {
            __half h = __float2half_rn(v);
            th[o] = __half_as_ushort(h);
            tl[o] = __half_as_ushort(__float2half_rn(v - __half2float(h)));
        } else {
            __nv_bfloat16 h = __float2bfloat16(v);
            th[o] = __bfloat16_as_ushort(h);
            tl[o] = __bfloat16_as_ushort(
                        __float2bfloat16(v - __bfloat162float(h)));
        }
    }
}

// ---------------------------------------------------------------------------
// 3-term split-bf16 GEMM for Q and K, fused via gridDim.z (z=0: Q, z=1: K).
// BM=BN=128, BK=32, 3-stage cp.async ring (validated R11 structure).
// Epilogue: dual-bf16 head-major [B,H,L,64].
// ---------------------------------------------------------------------------
#define STG (4 * 128 * 40)
#define GEMM_SMEM (3 * STG * 2)     // 122880 B

__global__ __launch_bounds__(256)
void gemm_qk(const __nv_bfloat16* __restrict__ Ah,
             const __nv_bfloat16* __restrict__ Al,
             const __nv_bfloat16* __restrict__ Bh0,
             const __nv_bfloat16* __restrict__ Bl0,
             const float* __restrict__ b0,
             __nv_bfloat16* __restrict__ oH0, __nv_bfloat16* __restrict__ oL0,
             const __nv_bfloat16* __restrict__ Bh1,
             const __nv_bfloat16* __restrict__ Bl1,
             const float* __restrict__ b1,
             __nv_bfloat16* __restrict__ oH1, __nv_bfloat16* __restrict__ oL1)
{
    const __nv_bfloat16* Bh = blockIdx.z ? Bh1 : Bh0;
    const __nv_bfloat16* Bl = blockIdx.z ? Bl1 : Bl0;
    const float* bias       = blockIdx.z ? b1  : b0;
    __nv_bfloat16* oH       = blockIdx.z ? oH1 : oH0;
    __nv_bfloat16* oL       = blockIdx.z ? oL1 : oL0;

    const int tid  = threadIdx.x;
    const int lane = tid & 31;
    const int warp = tid >> 5;
    const int wm   = warp >> 1;
    const int wn   = warp & 1;
    const int m0   = blockIdx.y * 128;
    const int n0   = blockIdx.x * 128;

    const int rb = tid >> 2;
    const int c8 = (tid & 3) << 3;

    const u32 smb = (u32)__cvta_generic_to_shared(dynsm);

    const int tr = lane & 7;
    const int arow = (wm * 32 + ((lane >> 3) & 1) * 8 + tr) * 40
                   + ((lane >> 4) & 1) * 8;
    int brow[4];
    #pragma unroll
    for (int p = 0; p < 4; ++p)
        brow[p] = (wn * 64 + p * 16 + ((lane >> 4) & 1) * 8 + tr) * 40
                + ((lane >> 3) & 1) * 8;

    float acc[2][8][4];
    #pragma unroll
    for (int mi = 0; mi < 2; ++mi)
        #pragma unroll
        for (int ni = 0; ni < 8; ++ni)
            #pragma unroll
            for (int r = 0; r < 4; ++r) acc[mi][ni][r] = 0.0f;

#define CP_CHUNK(slot, k0) do {                                             \
    u32 sb_ = smb + (u32)((slot) * STG) * 2;                                \
    _Pragma("unroll")                                                       \
    for (int q = 0; q < 2; ++q) {                                           \
        int row = rb + 64 * q;                                              \
        size_t ga = (size_t)(m0 + row) * DMODEL + (k0) + c8;                \
        size_t gb = (size_t)(n0 + row) * DMODEL + (k0) + c8;                \
        u32 so = (u32)(row * 40 + c8) * 2;                                  \
        cpasync16(sb_ + so,                 Ah + ga);                       \
        cpasync16(sb_ + 128 * 80 + so,      Al + ga);                       \
        cpasync16(sb_ + 2 * 128 * 80 + so,  Bh + gb);                       \
        cpasync16(sb_ + 3 * 128 * 80 + so,  Bl + gb);                       \
    } } while (0)

    CP_CHUNK(0, 0);  cpcommit();
    CP_CHUNK(1, 32); cpcommit();

    const int NK = DMODEL / 32;
    for (int kc = 0; kc < NK; ++kc) {
        cpwait<1>();
        __syncthreads();
        if (kc + 2 < NK) CP_CHUNK((kc + 2) % 3, (kc + 2) * 32);
        cpcommit();

        const u32 sb0 = smb + (u32)((kc % 3) * STG) * 2;
        const u32 sa_h = sb0;
        const u32 sa_l = sb0 + 128 * 80;
        const u32 sb_h = sb0 + 2 * 128 * 80;
        const u32 sb_l = sb0 + 3 * 128 * 80;

        #pragma unroll
        for (int ks = 0; ks < 2; ++ks) {
            const int ko = ks * 16;
            u32 fa_h0[4], fa_h1[4], fa_l0[4], fa_l1[4];
            ldm4(fa_h0, sa_h + (u32)(arow + ko) * 2);
            ldm4(fa_h1, sa_h + (u32)(arow + 640 + ko) * 2);
            ldm4(fa_l0, sa_l + (u32)(arow + ko) * 2);
            ldm4(fa_l1, sa_l + (u32)(arow + 640 + ko) * 2);
            #pragma unroll
            for (int p = 0; p < 4; ++p) {
                u32 fbh[4], fbl[4];
                ldm4(fbh, sb_h + (u32)(brow[p] + ko) * 2);
                ldm4(fbl, sb_l + (u32)(brow[p] + ko) * 2);
                mma16816(acc[0][2 * p],     fa_h0, fbh[0], fbh[1]);
                mma16816(acc[0][2 * p],     fa_h0, fbl[0], fbl[1]);
                mma16816(acc[0][2 * p],     fa_l0, fbh[0], fbh[1]);
                mma16816(acc[0][2 * p + 1], fa_h0, fbh[2], fbh[3]);
                mma16816(acc[0][2 * p + 1], fa_h0, fbl[2], fbl[3]);
                mma16816(acc[0][2 * p + 1], fa_l0, fbh[2], fbh[3]);
                mma16816(acc[1][2 * p],     fa_h1, fbh[0], fbh[1]);
                mma16816(acc[1][2 * p],     fa_h1, fbl[0], fbl[1]);
                mma16816(acc[1][2 * p],     fa_l1, fbh[0], fbh[1]);
                mma16816(acc[1][2 * p + 1], fa_h1, fbh[2], fbh[3]);
                mma16816(acc[1][2 * p + 1], fa_h1, fbl[2], fbl[3]);
                mma16816(acc[1][2 * p + 1], fa_l1, fbh[2], fbh[3]);
            }
        }
    }
#undef CP_CHUNK

    const int g  = lane >> 2;
    const int t2 = (lane & 3) * 2;
    #pragma unroll
    for (int mi = 0; mi < 2; ++mi) {
        #pragma unroll
        for (int ni = 0; ni < 8; ++ni) {
            int n = n0 + wn * 64 + ni * 8 + t2;
            float2 bb = *(const float2*)&bias[n];
            int m1 = m0 + wm * 32 + mi * 16 + g;
            int m2 = m1 + 8;
            float2 v0 = make_float2(acc[mi][ni][0] + bb.x, acc[mi][ni][1] + bb.y);
            float2 v1 = make_float2(acc[mi][ni][2] + bb.x, acc[mi][ni][3] + bb.y);
            int h_ = n >> 6, d_ = n & (DK - 1);
            int b1i = m1 >> 11, l1 = m1 & (SEQ - 1);
            int b2i = m2 >> 11, l2 = m2 & (SEQ - 1);
            size_t i1 = (((size_t)(b1i * NHEADS + h_) * SEQ + l1) << 6) + d_;
            size_t i2 = (((size_t)(b2i * NHEADS + h_) * SEQ + l2) << 6) + d_;
            u32 h32, l32, h33, l33;
            split2(v0.x, v0.y, h32, l32);
            split2(v1.x, v1.y, h33, l33);
            *(u32*)&oH[i1] = h32; *(u32*)&oL[i1] = l32;
            *(u32*)&oH[i2] = h33; *(u32*)&oL[i2] = l33;
        }
    }
}

// ---------------------------------------------------------------------------
// 2-term fp16 GEMM: out = A(single fp16) @ (Bh+Bl)^T + bias.
// Used for V projection (mode 1: dual-fp16 head-major out) and
// output projection (mode 0: fp32 out). 3-stage cp.async ring.
// ---------------------------------------------------------------------------
#define FSTG (3 * 128 * 40)
#define GEMM2_SMEM (3 * FSTG * 2)   // 92160 B

__global__ __launch_bounds__(256)
void gemm_f16(const __half* __restrict__ A,
              const __half* __restrict__ Bh,
              const __half* __restrict__ Bl,
              const float* __restrict__ bias,
              float* __restrict__ out,
              __half* __restrict__ oH, __half* __restrict__ oL, int mode)
{
    const int tid  = threadIdx.x;
    const int lane = tid & 31;
    const int warp = tid >> 5;
    const int wm   = warp >> 1;
    const int wn   = warp & 1;
    const int m0   = blockIdx.y * 128;
    const int n0   = blockIdx.x * 128;

    const int rb = tid >> 2;
    const int c8 = (tid & 3) << 3;

    const u32 smb = (u32)__cvta_generic_to_shared(dynsm);

    const int tr = lane & 7;
    const int arow = (wm * 32 + ((lane >> 3) & 1) * 8 + tr) * 40
                   + ((lane >> 4) & 1) * 8;
    int brow[4];
    #pragma unroll
    for (int p = 0; p < 4; ++p)
        brow[p] = (wn * 64 + p * 16 + ((lane >> 4) & 1) * 8 + tr) * 40
                + ((lane >> 3) & 1) * 8;

    float acc[2][8][4];
    #pragma unroll
    for (int mi = 0; mi < 2; ++mi)
        #pragma unroll
        for (int ni = 0; ni < 8; ++ni)
            #pragma unroll
            for (int r = 0; r < 4; ++r) acc[mi][ni][r] = 0.0f;

#define CP_CHUNK2(slot, k0) do {                                            \
    u32 sb_ = smb + (u32)((slot) * FSTG) * 2;                               \
    _Pragma("unroll")                                                       \
    for (int q = 0; q < 2; ++q) {                                           \
        int row = rb + 64 * q;                                              \
        size_t ga = (size_t)(m0 + row) * DMODEL + (k0) + c8;                \
        size_t gb = (size_t)(n0 + row) * DMODEL + (k0) + c8;                \
        u32 so = (u32)(row * 40 + c8) * 2;                                  \
        cpasync16(sb_ + so,                 A  + ga);                       \
        cpasync16(sb_ + 128 * 80 + so,      Bh + gb);                       \
        cpasync16(sb_ + 2 * 128 * 80 + so,  Bl + gb);                       \
    } } while (0)

    CP_CHUNK2(0, 0);  cpcommit();
    CP_CHUNK2(1, 32); cpcommit();

    const int NK = DMODEL / 32;
    for (int kc = 0; kc < NK; ++kc) {
        cpwait<1>();
        __syncthreads();
        if (kc + 2 < NK) CP_CHUNK2((kc + 2) % 3, (kc + 2) * 32);
        cpcommit();

        const u32 sb0 = smb + (u32)((kc % 3) * FSTG) * 2;
        const u32 sa  = sb0;
        const u32 sb_h = sb0 + 128 * 80;
        const u32 sb_l = sb0 + 2 * 128 * 80;

        #pragma unroll
        for (int ks = 0; ks < 2; ++ks) {
            const int ko = ks * 16;
            u32 fa0[4], fa1[4];
            ldm4(fa0, sa + (u32)(arow + ko) * 2);
            ldm4(fa1, sa + (u32)(arow + 640 + ko) * 2);
            #pragma unroll
            for (int p = 0; p < 4; ++p) {
                u32 fbh[4], fbl[4];
                ldm4(fbh, sb_h + (u32)(brow[p] + ko) * 2);
                ldm4(fbl, sb_l + (u32)(brow[p] + ko) * 2);
                mma16816h(acc[0][2 * p],     fa0, fbh[0], fbh[1]);
                mma16816h(acc[0][2 * p],     fa0, fbl[0], fbl[1]);
                mma16816h(acc[0][2 * p + 1], fa0, fbh[2], fbh[3]);
                mma16816h(acc[0][2 * p + 1], fa0, fbl[2], fbl[3]);
                mma16816h(acc[1][2 * p],     fa1, fbh[0], fbh[1]);
                mma16816h(acc[1][2 * p],     fa1, fbl[0], fbl[1]);
                mma16816h(acc[1][2 * p + 1], fa1, fbh[2], fbh[3]);
                mma16816h(acc[1][2 * p + 1], fa1, fbl[2], fbl[3]);
            }
        }
    }
#undef CP_CHUNK2

    const int g  = lane >> 2;
    const int t2 = (lane & 3) * 2;
    #pragma unroll
    for (int mi = 0; mi < 2; ++mi) {
        #pragma unroll
        for (int ni = 0; ni < 8; ++ni) {
            int n = n0 + wn * 64 + ni * 8 + t2;
            float2 bb = *(const float2*)&bias[n];
            int m1 = m0 + wm * 32 + mi * 16 + g;
            int m2 = m1 + 8;
            float2 v0 = make_float2(acc[mi][ni][0] + bb.x, acc[mi][ni][1] + bb.y);
            float2 v1 = make_float2(acc[mi][ni][2] + bb.x, acc[mi][ni][3] + bb.y);
            if (mode == 1) {
                int h_ = n >> 6, d_ = n & (DK - 1);
                int b1i = m1 >> 11, l1 = m1 & (SEQ - 1);
                int b2i = m2 >> 11, l2 = m2 & (SEQ - 1);
                size_t i1 = (((size_t)(b1i * NHEADS + h_) * SEQ + l1) << 6) + d_;
                size_t i2 = (((size_t)(b2i * NHEADS + h_) * SEQ + l2) << 6) + d_;
                u32 h32, l32, h33, l33;
                split2h(v0.x, v0.y, h32, l32);
                split2h(v1.x, v1.y, h33, l33);
                *(u32*)&oH[i1] = h32; *(u32*)&oL[i1] = l32;
                *(u32*)&oH[i2] = h33; *(u32*)&oL[i2] = l33;
            } else {
                *(float2*)&out[(size_t)m1 * DMODEL + n] = v0;
                *(float2*)&out[(size_t)m2 * DMODEL + n] = v1;
            }
        }
    }
}

// ---------------------------------------------------------------------------
// Causal flash-attention-2 (R11 structure). S: 3-term bf16 (Q,K dual bf16);
// PV: 2-term fp16 (P single fp16, V dual fp16). Epilogue: ctx single fp16.
// ---------------------------------------------------------------------------
#define KRS 72
#define ASTG (4 * 64 * KRS)
#define ATTN_SMEM (2 * ASTG * 2)

__global__ __launch_bounds__(256)
void attn_mma_kernel(const __nv_bfloat16* __restrict__ Qh_,
                     const __nv_bfloat16* __restrict__ Ql_,
                     const __nv_bfloat16* __restrict__ Kh_,
                     const __nv_bfloat16* __restrict__ Kl_,
                     const __half* __restrict__ Vh_,
                     const __half* __restrict__ Vl_,
                     __half* __restrict__ Cf)
{
    const int tid  = threadIdx.x;
    const int lane = tid & 31;
    const int warp = tid >> 5;
    const int g    = lane >> 2;
    const int t2   = (lane & 3) * 2;
    const int bh   = blockIdx.y;
    const int qt   = (int)gridDim.x - 1 - (int)blockIdx.x;
    const int q0   = qt * 128;
    const size_t base = (size_t)bh * SEQ * DK;

    const u32 smb = (u32)__cvta_generic_to_shared(dynsm);
    const u32 A0 = smb;
    const u32 A1 = smb + (u32)(64 * KRS) * 2;
    const u32 A2 = smb + (u32)(2 * 64 * KRS) * 2;
    const u32 A3 = smb + (u32)(3 * 64 * KRS) * 2;

    #pragma unroll
    for (int q = 0; q < 4; ++q) {
        int idx = tid + q * 256;
        int row = idx >> 3;
        int c   = (idx & 7) << 3;
        size_t gq = base + (size_t)(q0 + row) * DK + c;
        u32 so = (u32)((row & 63) * KRS + c) * 2;
        if (row < 64) {
            *(uint4*)(dynsm + ((so >> 1)))                = *(const uint4*)(Qh_ + gq);
            *(uint4*)(dynsm + (2 * 64 * KRS) + (so >> 1)) = *(const uint4*)(Ql_ + gq);
        } else {
            *(uint4*)(dynsm + (64 * KRS) + (so >> 1))     = *(const uint4*)(Qh_ + gq);
            *(uint4*)(dynsm + (3 * 64 * KRS) + (so >> 1)) = *(const uint4*)(Ql_ + gq);
        }
    }
    __syncthreads();

    const int tr = lane & 7;
    const int aoff = (((lane >> 3) & 1) * 8 + tr) * KRS + ((lane >> 4) & 1) * 8;

    u32 qh[4][4], ql[4][4];
    {
        const int rl = warp * 16;
        const u32 bh_u = (rl < 64) ? A0 : A1;
        const u32 bl_u = (rl < 64) ? A2 : A3;
        const int rbase = (rl & 63) * KRS;
        #pragma unroll
        for (int ks = 0; ks < 4; ++ks) {
            ldm4(qh[ks], bh_u + (u32)(rbase + aoff + ks * 16) * 2);
            ldm4(ql[ks], bl_u + (u32)(rbase + aoff + ks * 16) * 2);
        }
    }
    __syncthreads();

#define CP_KV(slot, k0) do {                                                \
    u32 sb_ = smb + (u32)((slot) * ASTG) * 2;                               \
    _Pragma("unroll")                                                       \
    for (int q = 0; q < 2; ++q) {                                           \
        int idx = tid + q * 256;                                            \
        int row = idx >> 3;                                                 \
        int c   = (idx & 7) << 3;                                           \
        size_t gk = base + (size_t)((k0) + row) * DK + c;                   \
        u32 so = (u32)(row * KRS + c) * 2;                                  \
        cpasync16(sb_ + so,                     Kh_ + gk);                  \
        cpasync16(sb_ + (u32)(64*KRS)*2 + so,   Kl_ + gk);                  \
        cpasync16(sb_ + (u32)(2*64*KRS)*2 + so, Vh_ + gk);                  \
        cpasync16(sb_ + (u32)(3*64*KRS)*2 + so, Vl_ + gk);                  \
    } } while (0)

    int brow[4];
    #pragma unroll
    for (int p = 0; p < 4; ++p)
        brow[p] = (p * 16 + ((lane >> 4) & 1) * 8 + tr) * KRS
                + ((lane >> 3) & 1) * 8;
    const int vt = lane >> 3;
    const int voff = ((vt & 1) * 8 + tr) * KRS + (vt >> 1) * 8;

    float oacc[8][4];
    #pragma unroll
    for (int nf = 0; nf < 8; ++nf)
        #pragma unroll
        for (int r = 0; r < 4; ++r) oacc[nf][r] = 0.0f;
    float m_i[2] = {-1e30f, -1e30f};
    float l_i[2] = {0.0f, 0.0f};

    const int jmax = 2 * qt + 2;
    CP_KV(0, 0); cpcommit();

    for (int j = 0; j < jmax; ++j) {
        if (j + 1 < jmax) CP_KV((j + 1) & 1, (j + 1) * 64);
        cpcommit();
        cpwait<1>();
        __syncthreads();

        const u32 sb0 = smb + (u32)((j & 1) * ASTG) * 2;
        const u32 uK_h = sb0;
        const u32 uK_l = sb0 + (u32)(64 * KRS) * 2;
        const u32 uV_h = sb0 + (u32)(2 * 64 * KRS) * 2;
        const u32 uV_l = sb0 + (u32)(3 * 64 * KRS) * 2;
        const int k0 = j * 64;

        const bool active = (q0 + warp * 16 + 15 >= k0);
        if (active) {
            float sacc[8][4];
            #pragma unroll
            for (int nf = 0; nf < 8; ++nf)
                #pragma unroll
                for (int r = 0; r < 4; ++r) sacc[nf][r] = 0.0f;

            #pragma unroll
            for (int ks = 0; ks < 4; ++ks) {
                const int ko = ks * 16;
                #pragma unroll
                for (int p = 0; p < 4; ++p) {
                    u32 fkh[4], fkl[4];
                    ldm4(fkh, uK_h + (u32)(brow[p] + ko) * 2);
                    ldm4(fkl, uK_l + (u32)(brow[p] + ko) * 2);
                    mma16816(sacc[2 * p],     qh[ks], fkh[0], fkh[1]);
                    mma16816(sacc[2 * p],     qh[ks], fkl[0], fkl[1]);
                    mma16816(sacc[2 * p],     ql[ks], fkh[0], fkh[1]);
                    mma16816(sacc[2 * p + 1], qh[ks], fkh[2], fkh[3]);
                    mma16816(sacc[2 * p + 1], qh[ks], fkl[2], fkl[3]);
                    mma16816(sacc[2 * p + 1], ql[ks], fkh[2], fkh[3]);
                }
            }

            const int r0 = q0 + warp * 16 + g;
            if (j >= 2 * qt) {
                #pragma unroll
                for (int nf = 0; nf < 8; ++nf) {
                    int col = k0 + nf * 8 + t2;
                    sacc[nf][0] = (col     > r0)     ? -1e30f : sacc[nf][0] * 0.125f;
                    sacc[nf][1] = (col + 1 > r0)     ? -1e30f : sacc[nf][1] * 0.125f;
                    sacc[nf][2] = (col     > r0 + 8) ? -1e30f : sacc[nf][2] * 0.125f;
                    sacc[nf][3] = (col + 1 > r0 + 8) ? -1e30f : sacc[nf][3] * 0.125f;
                }
            } else {
                #pragma unroll
                for (int nf = 0; nf < 8; ++nf)
                    #pragma unroll
                    for (int r = 0; r < 4; ++r) sacc[nf][r] *= 0.125f;
            }

            #pragma unroll
            for (int r = 0; r < 2; ++r) {
                float mt = -1e30f;
                #pragma unroll
                for (int nf = 0; nf < 8; ++nf)
                    mt = fmaxf(mt, fmaxf(sacc[nf][2 * r], sacc[nf][2 * r + 1]));
                mt = fmaxf(mt, __shfl_xor_sync(0xffffffffu, mt, 1));
                mt = fmaxf(mt, __shfl_xor_sync(0xffffffffu, mt, 2));
                float mn = fmaxf(m_i[r], mt);
                float corr = __expf(m_i[r] - mn);
                m_i[r] = mn;
                float rs = 0.0f;
                #pragma unroll
                for (int nf = 0; nf < 8; ++nf) {
                    float p0 = __expf(sacc[nf][2 * r] - mn);
                    float p1 = __expf(sacc[nf][2 * r + 1] - mn);
                    sacc[nf][2 * r] = p0;
                    sacc[nf][2 * r + 1] = p1;
                    rs += p0 + p1;
                    oacc[nf][2 * r] *= corr;
                    oacc[nf][2 * r + 1] *= corr;
                }
                rs += __shfl_xor_sync(0xffffffffu, rs, 1);
                rs += __shfl_xor_sync(0xffffffffu, rs, 2);
                l_i[r] = l_i[r] * corr + rs;
            }

            // PV: P single fp16, V dual fp16 (2 terms).
            #pragma unroll
            for (int ks = 0; ks < 4; ++ks) {
                u32 ph[4];
                ph[0] = packh2(sacc[2 * ks][0],     sacc[2 * ks][1]);
                ph[1] = packh2(sacc[2 * ks][2],     sacc[2 * ks][3]);
                ph[2] = packh2(sacc[2 * ks + 1][0], sacc[2 * ks + 1][1]);
                ph[3] = packh2(sacc[2 * ks + 1][2], sacc[2 * ks + 1][3]);
                const int krow = ks * 16;
                #pragma unroll
                for (int p = 0; p < 4; ++p) {
                    u32 fvh[4], fvl[4];
                    u32 va = (u32)((krow * KRS + p * 16 + voff)) * 2;
                    ldm4t(fvh, uV_h + va);
                    ldm4t(fvl, uV_l + va);
                    mma16816h(oacc[2 * p],     ph, fvh[0], fvh[1]);
                    mma16816h(oacc[2 * p],     ph, fvl[0], fvl[1]);
                    mma16816h(oacc[2 * p + 1], ph, fvh[2], fvh[3]);
                    mma16816h(oacc[2 * p + 1], ph, fvl[2], fvl[3]);
                }
            }
        }
        __syncthreads();
    }
#undef CP_KV

    // normalize + write ctx as single fp16 [B, L, 1024]
    const int b_ = bh >> 4;
    const int h_ = bh & 15;
    const float inv0 = 1.0f / l_i[0];
    const float inv1 = 1.0f / l_i[1];
    const int row0 = q0 + warp * 16 + g;
    #pragma unroll
    for (int nf = 0; nf < 8; ++nf) {
        int d = nf * 8 + t2;
        size_t i0 = ((size_t)(b_ * SEQ + row0)) * DMODEL + h_ * DK + d;
        size_t i1 = ((size_t)(b_ * SEQ + row0 + 8)) * DMODEL + h_ * DK + d;
        *(u32*)&Cf[i0] = packh2(oacc[nf][0] * inv0, oacc[nf][1] * inv0);
        *(u32*)&Cf[i1] = packh2(oacc[nf][2] * inv1, oacc[nf][3] * inv1);
    }
}

// ---------------------------------------------------------------------------
extern "C" void kernel_launch(void* const* d_in, const int* in_sizes, int n_in,
                              void* d_out, int out_size)
{
    (void)in_sizes; (void)n_in; (void)out_size;
    const float* x  = (const float*)d_in[0];
    const float* Wq = (const float*)d_in[2];
    const float* bq = (const float*)d_in[3];
    const float* Wk = (const float*)d_in[4];
    const float* bk = (const float*)d_in[5];
    const float* Wv = (const float*)d_in[6];
    const float* bv = (const float*)d_in[7];
    const float* Wo = (const float*)d_in[8];
    const float* bo = (const float*)d_in[9];
    float* out = (float*)d_out;

    __nv_bfloat16 *ah, *al, *Qh, *Ql, *Kh, *Kl;
    __half *af, *Vh, *Vl;
    u16 *wh, *wl;
    cudaGetSymbolAddress((void**)&ah, g_ah);
    cudaGetSymbolAddress((void**)&al, g_al);
    cudaGetSymbolAddress((void**)&af, g_af);
    cudaGetSymbolAddress((void**)&wh, g_wh);
    cudaGetSymbolAddress((void**)&wl, g_wl);
    cudaGetSymbolAddress((void**)&Qh, g_Qh);
    cudaGetSymbolAddress((void**)&Ql, g_Ql);
    cudaGetSymbolAddress((void**)&Kh, g_Kh);
    cudaGetSymbolAddress((void**)&Kl, g_Kl);
    cudaGetSymbolAddress((void**)&Vh, g_Vh);
    cudaGetSymbolAddress((void**)&Vl, g_Vl);

    cudaFuncSetAttribute(gemm_qk,
                         cudaFuncAttributeMaxDynamicSharedMemorySize, GEMM_SMEM);
    cudaFuncSetAttribute(gemm_f16,
                         cudaFuncAttributeMaxDynamicSharedMemorySize, GEMM2_SMEM);
    cudaFuncSetAttribute(attn_mma_kernel,
                         cudaFuncAttributeMaxDynamicSharedMemorySize, ATTN_SMEM);

    const size_t WSZ = (size_t)DMODEL * DMODEL;
    const int n4 = MROWS * DMODEL / 4;

    split_kernel<<<n4 / 256, 256>>>((const float4*)x, (uint2*)ah, (uint2*)al,
                                    (uint2*)af);
    dim3 wgrid(DMODEL / 32, DMODEL / 32), wblk(32, 8);
    wsplit_kernel<<<wgrid, wblk>>>(Wq, wh + 0 * WSZ, wl + 0 * WSZ, 0);
    wsplit_kernel<<<wgrid, wblk>>>(Wk, wh + 1 * WSZ, wl + 1 * WSZ, 0);
    wsplit_kernel<<<wgrid, wblk>>>(Wv, wh + 2 * WSZ, wl + 2 * WSZ, 1);
    wsplit_kernel<<<wgrid, wblk>>>(Wo, wh + 3 * WSZ, wl + 3 * WSZ, 1);

    // Q and K projections fused (z=0 -> Q, z=1 -> K), 3-term bf16.
    dim3 gqk(DMODEL / 128, MROWS / 128, 2);
    gemm_qk<<<gqk, 256, GEMM_SMEM>>>(
        ah, al,
        (const __nv_bfloat16*)(wh + 0 * WSZ), (const __nv_bfloat16*)(wl + 0 * WSZ),
        bq, Qh, Ql,
        (const __nv_bfloat16*)(wh + 1 * WSZ), (const __nv_bfloat16*)(wl + 1 * WSZ),
        bk, Kh, Kl);

    // V projection, 2-term fp16 -> dual-fp16 head-major.
    dim3 gg(DMODEL / 128, MROWS / 128);
    gemm_f16<<<gg, 256, GEMM2_SMEM>>>(af,
        (const __half*)(wh + 2 * WSZ), (const __half*)(wl + 2 * WSZ),
        bv, nullptr, Vh, Vl, 1);

    // Attention writes ctx (single fp16) into af.
    attn_mma_kernel<<<dim3(SEQ / 128, BATCH * NHEADS), 256, ATTN_SMEM>>>(
        Qh, Ql, Kh, Kl, Vh, Vl, af);

    // Output projection, 2-term fp16 -> fp32.
    gemm_f16<<<gg, 256, GEMM2_SMEM>>>(af,
        (const __half*)(wh + 3 * WSZ), (const __half*)(wl + 3 * WSZ),
        bo, out, nullptr, nullptr, 0);
}